// round 12
// baseline (speedup 1.0000x reference)
#include <cuda_runtime.h>
#include <math.h>

#define N_NODES  100000
#define N_EDGES  1000000
#define N_GRAPHS 2048
#define F_IN     78
#define DIM      32
#define T_DIM    208
#define H1       170
#define H2       128
#define BN_EPS   1e-5f
#define DEG_CAP  64

// ---------------- scratch (device globals; no allocation allowed) ----------
__device__ float  d_proj[N_NODES * DIM];
__device__ float  d_hA[N_NODES * DIM];
__device__ float  d_hB[N_NODES * DIM];
__device__ double d_stat[3 * 2 * DIM];   // per layer: [sums(32), sumsq(32)]
__device__ float  d_t1[N_GRAPHS * H1];
__device__ float  d_t2[N_GRAPHS * H2];
__device__ float  d_AB[2 * T_DIM];
__device__ int    d_deg[N_NODES];        // zero at load; re-zeroed by k_tail
__device__ int    d_adj[N_NODES * DEG_CAP];
__device__ int    d_goff[N_GRAPHS + 1];

#define EDGE_BLOCKS  ((N_EDGES + 255) / 256)             // 3907
#define GOFF_BLOCKS  ((N_GRAPHS + 1 + 255) / 256)        // 9
#define T_BLOCKS     (N_GRAPHS / 16)                     // 128
#define MLP_BLOCKS   760                                 // +128 = 888 = 6*148 (one wave)
#define PROJ_BLOCKS  1024

// ---------------- build: adjacency + goff + target BN stats + stat zeroing
__global__ void k_build(const int* __restrict__ src, const int* __restrict__ dst,
                        int* __restrict__ deg, int* __restrict__ adj,
                        const int* __restrict__ batch, int* __restrict__ goff,
                        const float* __restrict__ target,
                        const float* __restrict__ g1, const float* __restrict__ be1,
                        float* __restrict__ AB,
                        double* __restrict__ stat) {
    int b = blockIdx.x;
    if (b < EDGE_BLOCKS) {
        int i = b * 256 + threadIdx.x;
        if (i < N_EDGES) {
            int d = dst[i];
            int c = atomicAdd(&deg[d], 1);
            if (c < DEG_CAP) adj[d * DEG_CAP + c] = src[i];
        }
        return;
    }
    if (b < EDGE_BLOCKS + GOFF_BLOCKS) {
        int g = (b - EDGE_BLOCKS) * 256 + threadIdx.x;
        if (g > N_GRAPHS) return;
        int lo = 0, hi = N_NODES;
        while (lo < hi) { int mid = (lo + hi) >> 1; if (batch[mid] < g) lo = mid + 1; else hi = mid; }
        goff[g] = lo;
        return;
    }
    if (b < EDGE_BLOCKS + GOFF_BLOCKS + 1) {
        if (threadIdx.x < 3 * 2 * DIM) stat[threadIdx.x] = 0.0;
        return;
    }
    // target BN stats: one block per column
    int c = b - EDGE_BLOCKS - GOFF_BLOCKS - 1;
    float s = 0.f, q = 0.f;
    for (int r = threadIdx.x; r < N_GRAPHS; r += blockDim.x) {
        float v = target[r * T_DIM + c];
        s += v;
        q = fmaf(v, v, q);
    }
    __shared__ float ssm[256], sqm[256];
    ssm[threadIdx.x] = s; sqm[threadIdx.x] = q;
    __syncthreads();
    for (int st = 128; st > 0; st >>= 1) {
        if (threadIdx.x < st) { ssm[threadIdx.x] += ssm[threadIdx.x + st]; sqm[threadIdx.x] += sqm[threadIdx.x + st]; }
        __syncthreads();
    }
    if (threadIdx.x == 0) {
        float m = ssm[0] / (float)N_GRAPHS;
        float v = sqm[0] / (float)N_GRAPHS - m * m;
        float inv = rsqrtf(v + BN_EPS);
        float A = g1[c] * inv;
        AB[c]         = A;
        AB[T_DIM + c] = be1[c] - m * A;
    }
}

// ---------------- node kernels ----------------------------------------------

// proj = x @ W  (x: [N,78], W: [78,32]) ; one warp per node, grid-stride
__global__ void k_proj_in(const float* __restrict__ x,
                          const float* __restrict__ W,
                          float* __restrict__ out) {
    __shared__ float Ws[F_IN * DIM];
    for (int i = threadIdx.x; i < F_IN * DIM; i += blockDim.x) Ws[i] = W[i];
    __syncthreads();
    int lane = threadIdx.x & 31;
    int gwarp = (blockIdx.x * blockDim.x + threadIdx.x) >> 5;
    const int nwarps = (PROJ_BLOCKS * 256) >> 5;
    for (int n = gwarp; n < N_NODES; n += nwarps) {
        const float* xr = x + (size_t)n * F_IN;
        float r0 = xr[lane];
        float r1 = xr[32 + lane];
        float r2 = (lane < F_IN - 64) ? xr[64 + lane] : 0.f;
        float acc = 0.f;
        #pragma unroll
        for (int k = 0; k < 32; k++)
            acc = fmaf(__shfl_sync(0xffffffffu, r0, k), Ws[k * DIM + lane], acc);
        #pragma unroll
        for (int k = 0; k < 32; k++)
            acc = fmaf(__shfl_sync(0xffffffffu, r1, k), Ws[(32 + k) * DIM + lane], acc);
        #pragma unroll
        for (int k = 0; k < F_IN - 64; k++)
            acc = fmaf(__shfl_sync(0xffffffffu, r2, k), Ws[(64 + k) * DIM + lane], acc);
        out[n * DIM + lane] = acc;
    }
}

// Target-branch blocks (TP: 1=t1 GEMM, 2=t2 softmax); 256-thread blocks
template <int TP>
__device__ __forceinline__ void target_branch(int tb,
                          const float* __restrict__ tin,
                          const float* __restrict__ AB,
                          const float* __restrict__ Wt,
                          const float* __restrict__ bt,
                          float* __restrict__ tout) {
    if (TP == 1) {
        __shared__ float tn[T_DIM];
        for (int rr = 0; rr < 16; rr++) {
            int row = tb * 16 + rr;
            __syncthreads();
            for (int c = threadIdx.x; c < T_DIM; c += 256)
                tn[c] = fmaf(tin[row * T_DIM + c], AB[c], AB[T_DIM + c]);
            __syncthreads();
            for (int j = threadIdx.x; j < H1; j += 256) {
                float acc = bt[j];
                #pragma unroll 4
                for (int c = 0; c < T_DIM; c++) acc = fmaf(tn[c], Wt[c * H1 + j], acc);
                tout[row * H1 + j] = acc;
            }
        }
    } else {
        __shared__ float t1s[H1];
        __shared__ float red2[4];
        int j = threadIdx.x;
        bool act = j < 128;
        int wid = j >> 5, lane = j & 31;
        for (int rr = 0; rr < 16; rr++) {
            int row = tb * 16 + rr;
            __syncthreads();
            for (int c = j; c < H1; c += 256) t1s[c] = tin[row * H1 + c];
            __syncthreads();
            float acc = 0.f;
            if (act) {
                acc = bt[j];
                #pragma unroll 2
                for (int c = 0; c < H1; c++) acc = fmaf(t1s[c], Wt[c * H2 + j], acc);
                float m = acc;
                for (int o = 16; o > 0; o >>= 1) m = fmaxf(m, __shfl_xor_sync(0xffffffffu, m, o));
                if (lane == 0) red2[wid] = m;
            }
            __syncthreads();
            float e = 0.f, s = 0.f;
            if (act) {
                float mm = fmaxf(fmaxf(red2[0], red2[1]), fmaxf(red2[2], red2[3]));
                e = expf(acc - mm);
                s = e;
                for (int o = 16; o > 0; o >>= 1) s += __shfl_xor_sync(0xffffffffu, s, o);
            }
            __syncthreads();
            if (act && lane == 0) red2[wid] = s;
            __syncthreads();
            if (act) {
                float ssum = red2[0] + red2[1] + red2[2] + red2[3];
                tout[row * H2 + j] = e / ssum;
            }
        }
    }
}

// Fused GIN layer, 4 nodes per warp / float4 per lane (8 lanes per node).
// Gather uses register-held int4 index quads (NO shfl in the address path).
// NMAT=1 (layer 1): z = relu(gather(proj)+b1); out = elu(z@W2 + b2)
// NMAT=2 (layers 2/3): z = gather(h); r = relu(z@W1f + (1+deg)*badd + b1);
//                      out = relu(r@W2 + b2).  W1f = diag(sc)@W1 (BN fold).
template <int NMAT, int TP>
__global__ void __launch_bounds__(256, 6)
k_agg(const float* __restrict__ hin,
      const int* __restrict__ deg,
      const int* __restrict__ adj,
      const double* __restrict__ statp,
      const float* __restrict__ W1,
      const float* __restrict__ b1,
      const float* __restrict__ W2,
      const float* __restrict__ b2,
      float* __restrict__ hout,
      double* __restrict__ stat,
      const float* __restrict__ tin,
      const float* __restrict__ AB,
      const float* __restrict__ Wt,
      const float* __restrict__ bt,
      float* __restrict__ tout) {
    if (TP != 0 && blockIdx.x < T_BLOCKS) {
        target_branch<TP>(blockIdx.x, tin, AB, Wt, bt, tout);
        return;
    }
    const int abid = (TP != 0) ? (blockIdx.x - T_BLOCKS) : blockIdx.x;

    __shared__ float4 W1q[DIM][8];
    __shared__ float4 W2q[DIM][8];
    __shared__ float4 baddq[8], b1q[8], b2q[8];
    __shared__ float  red[2 * DIM];

    float* W1f   = (float*)W1q;
    float* W2f   = (float*)W2q;
    float* badds = (float*)baddq;
    float* b1s   = (float*)b1q;
    float* b2s   = (float*)b2q;
    const int tid = threadIdx.x;

    if (tid < 32) {
        int j = tid;
        if (NMAT == 2) {
            double m = statp[j] * (1.0 / N_NODES);
            double v = statp[DIM + j] * (1.0 / N_NODES) - m * m;
            float sc = (float)(1.0 / sqrt(v + (double)BN_EPS));
            float sh = (float)(-m) * sc;
            float bacc = 0.f;
            #pragma unroll
            for (int k = 0; k < DIM; k++) {
                float w = W1[k * DIM + j];
                W1f[k * DIM + j] = __shfl_sync(0xffffffffu, sc, k) * w;
                bacc = fmaf(__shfl_sync(0xffffffffu, sh, k), w, bacc);
            }
            badds[j] = bacc;
        }
        b1s[j] = b1[j];
        b2s[j] = b2[j];
    }
    for (int i = tid; i < DIM * DIM; i += 256) W2f[i] = W2[i];
    if (tid < 2 * DIM) red[tid] = 0.f;
    __syncthreads();

    const int lane = tid & 31;
    const int g    = lane >> 3;    // node group 0..3
    const int sl   = lane & 7;     // feature quad 0..7
    const int gb   = g << 3;
    const int gwarp = (abid * 256 + tid) >> 5;
    const int stride4 = (MLP_BLOCKS * 8) * 4;
    float4 lsum = make_float4(0.f, 0.f, 0.f, 0.f);
    float4 lsq  = make_float4(0.f, 0.f, 0.f, 0.f);

    for (int n4 = gwarp * 4; n4 < N_NODES; n4 += stride4) {
        const int n = n4 + g;
        const int dT = deg[n];
        int dn = dT > DEG_CAP ? DEG_CAP : dT;
        const int* an = adj + (size_t)n * DEG_CAP;

        float4 z = *(const float4*)(hin + (size_t)n * DIM + sl * 4);

        // Gather: per 8-neighbor batch, indices come from two int4 broadcast
        // loads (uniform within the 8-lane group) — no SHFL in the address path.
        for (int base = 0; base < dn; base += 8) {
            int4 i0 = *(const int4*)(an + base);
            int4 i1 = *(const int4*)(an + base + 4);
            int rem = dn - base;
            if (rem >= 8) {
                float4 t0 = *(const float4*)(hin + (size_t)i0.x * DIM + sl * 4);
                float4 t1 = *(const float4*)(hin + (size_t)i0.y * DIM + sl * 4);
                float4 t2 = *(const float4*)(hin + (size_t)i0.z * DIM + sl * 4);
                float4 t3 = *(const float4*)(hin + (size_t)i0.w * DIM + sl * 4);
                float4 t4 = *(const float4*)(hin + (size_t)i1.x * DIM + sl * 4);
                float4 t5 = *(const float4*)(hin + (size_t)i1.y * DIM + sl * 4);
                float4 t6 = *(const float4*)(hin + (size_t)i1.z * DIM + sl * 4);
                float4 t7 = *(const float4*)(hin + (size_t)i1.w * DIM + sl * 4);
                z.x += ((t0.x + t1.x) + (t2.x + t3.x)) + ((t4.x + t5.x) + (t6.x + t7.x));
                z.y += ((t0.y + t1.y) + (t2.y + t3.y)) + ((t4.y + t5.y) + (t6.y + t7.y));
                z.z += ((t0.z + t1.z) + (t2.z + t3.z)) + ((t4.z + t5.z) + (t6.z + t7.z));
                z.w += ((t0.w + t1.w) + (t2.w + t3.w)) + ((t4.w + t5.w) + (t6.w + t7.w));
            } else {
                #pragma unroll
                for (int k = 0; k < 7; k++) {
                    if (k < rem) {
                        int s = (k < 4) ? ((const int*)&i0)[k] : ((const int*)&i1)[k - 4];
                        float4 t = *(const float4*)(hin + (size_t)s * DIM + sl * 4);
                        z.x += t.x; z.y += t.y; z.z += t.z; z.w += t.w;
                    }
                }
            }
        }

        if (NMAT == 1) {
            float4 bb1 = b1q[sl];
            z.x = fmaxf(z.x + bb1.x, 0.f);
            z.y = fmaxf(z.y + bb1.y, 0.f);
            z.z = fmaxf(z.z + bb1.z, 0.f);
            z.w = fmaxf(z.w + bb1.w, 0.f);
        } else {
            // matvec1: acc1 = z @ W1f + (1+deg)*badd + b1 ; z := relu(acc1)
            float df = (float)(1 + dT);
            float4 bd  = baddq[sl];
            float4 bb1 = b1q[sl];
            float4 a;
            a.x = fmaf(df, bd.x, bb1.x);
            a.y = fmaf(df, bd.y, bb1.y);
            a.z = fmaf(df, bd.z, bb1.z);
            a.w = fmaf(df, bd.w, bb1.w);
            #pragma unroll
            for (int kq = 0; kq < 8; kq++) {
                float zx = __shfl_sync(0xffffffffu, z.x, gb + kq);
                float zy = __shfl_sync(0xffffffffu, z.y, gb + kq);
                float zz = __shfl_sync(0xffffffffu, z.z, gb + kq);
                float zw = __shfl_sync(0xffffffffu, z.w, gb + kq);
                float4 w;
                w = W1q[4 * kq + 0][sl];
                a.x = fmaf(zx, w.x, a.x); a.y = fmaf(zx, w.y, a.y);
                a.z = fmaf(zx, w.z, a.z); a.w = fmaf(zx, w.w, a.w);
                w = W1q[4 * kq + 1][sl];
                a.x = fmaf(zy, w.x, a.x); a.y = fmaf(zy, w.y, a.y);
                a.z = fmaf(zy, w.z, a.z); a.w = fmaf(zy, w.w, a.w);
                w = W1q[4 * kq + 2][sl];
                a.x = fmaf(zz, w.x, a.x); a.y = fmaf(zz, w.y, a.y);
                a.z = fmaf(zz, w.z, a.z); a.w = fmaf(zz, w.w, a.w);
                w = W1q[4 * kq + 3][sl];
                a.x = fmaf(zw, w.x, a.x); a.y = fmaf(zw, w.y, a.y);
                a.z = fmaf(zw, w.z, a.z); a.w = fmaf(zw, w.w, a.w);
            }
            z.x = fmaxf(a.x, 0.f);
            z.y = fmaxf(a.y, 0.f);
            z.z = fmaxf(a.z, 0.f);
            z.w = fmaxf(a.w, 0.f);
        }

        // matvec2: out = z @ W2 + b2
        float4 o = b2q[sl];
        #pragma unroll
        for (int kq = 0; kq < 8; kq++) {
            float zx = __shfl_sync(0xffffffffu, z.x, gb + kq);
            float zy = __shfl_sync(0xffffffffu, z.y, gb + kq);
            float zz = __shfl_sync(0xffffffffu, z.z, gb + kq);
            float zw = __shfl_sync(0xffffffffu, z.w, gb + kq);
            float4 w;
            w = W2q[4 * kq + 0][sl];
            o.x = fmaf(zx, w.x, o.x); o.y = fmaf(zx, w.y, o.y);
            o.z = fmaf(zx, w.z, o.z); o.w = fmaf(zx, w.w, o.w);
            w = W2q[4 * kq + 1][sl];
            o.x = fmaf(zy, w.x, o.x); o.y = fmaf(zy, w.y, o.y);
            o.z = fmaf(zy, w.z, o.z); o.w = fmaf(zy, w.w, o.w);
            w = W2q[4 * kq + 2][sl];
            o.x = fmaf(zz, w.x, o.x); o.y = fmaf(zz, w.y, o.y);
            o.z = fmaf(zz, w.z, o.z); o.w = fmaf(zz, w.w, o.w);
            w = W2q[4 * kq + 3][sl];
            o.x = fmaf(zw, w.x, o.x); o.y = fmaf(zw, w.y, o.y);
            o.z = fmaf(zw, w.z, o.z); o.w = fmaf(zw, w.w, o.w);
        }
        if (NMAT == 1) {
            o.x = (o.x > 0.f) ? o.x : expm1f(o.x);
            o.y = (o.y > 0.f) ? o.y : expm1f(o.y);
            o.z = (o.z > 0.f) ? o.z : expm1f(o.z);
            o.w = (o.w > 0.f) ? o.w : expm1f(o.w);
        } else {
            o.x = fmaxf(o.x, 0.f);
            o.y = fmaxf(o.y, 0.f);
            o.z = fmaxf(o.z, 0.f);
            o.w = fmaxf(o.w, 0.f);
        }
        *(float4*)(hout + (size_t)n * DIM + sl * 4) = o;
        lsum.x += o.x; lsq.x = fmaf(o.x, o.x, lsq.x);
        lsum.y += o.y; lsq.y = fmaf(o.y, o.y, lsq.y);
        lsum.z += o.z; lsq.z = fmaf(o.z, o.z, lsq.z);
        lsum.w += o.w; lsq.w = fmaf(o.w, o.w, lsq.w);
    }

    atomicAdd(&red[4 * sl + 0], lsum.x);
    atomicAdd(&red[4 * sl + 1], lsum.y);
    atomicAdd(&red[4 * sl + 2], lsum.z);
    atomicAdd(&red[4 * sl + 3], lsum.w);
    atomicAdd(&red[DIM + 4 * sl + 0], lsq.x);
    atomicAdd(&red[DIM + 4 * sl + 1], lsq.y);
    atomicAdd(&red[DIM + 4 * sl + 2], lsq.z);
    atomicAdd(&red[DIM + 4 * sl + 3], lsq.w);
    __syncthreads();
    if (tid < 2 * DIM)
        atomicAdd(&stat[tid], (double)red[tid]);
}

// Fused graph tail: inline layer-3 BN stats + pool + g2 + head; also re-zeroes deg.
__global__ void k_tail(const float* __restrict__ h,
                       const double* __restrict__ statp,
                       const int* __restrict__ goff,
                       const float* __restrict__ Wn2, const float* __restrict__ bn2b,
                       const float* __restrict__ t2,
                       const float* __restrict__ W4, const float* __restrict__ b4,
                       const float* __restrict__ W5, const float* __restrict__ b5,
                       float* __restrict__ outg,
                       float* __restrict__ out,
                       int* __restrict__ deg) {
    __shared__ float ss_s[2 * DIM];
    __shared__ float pacc[4][DIM];
    __shared__ float gs[DIM];
    __shared__ float xc[256];
    __shared__ float red[4];
    int b = blockIdx.x;
    int j = threadIdx.x;
    int wid = j >> 5, lane = j & 31;
    int zi = b * 128 + j;
    if (zi < N_NODES) deg[zi] = 0;
    if (j < 32) {
        double m = statp[j] * (1.0 / N_NODES);
        double v = statp[DIM + j] * (1.0 / N_NODES) - m * m;
        float sc = (float)(1.0 / sqrt(v + (double)BN_EPS));
        ss_s[j]       = sc;
        ss_s[DIM + j] = (float)(-m) * sc;
    }
    __syncthreads();
    int s0 = goff[b], s1 = goff[b + 1];
    float acc = 0.f;
    for (int n = s0 + wid; n < s1; n += 4) acc += h[n * DIM + lane];
    pacc[wid][lane] = acc;
    __syncthreads();
    if (wid == 0) {
        float a = pacc[0][lane] + pacc[1][lane] + pacc[2][lane] + pacc[3][lane];
        gs[lane] = fmaf(ss_s[lane], a, ss_s[DIM + lane] * (float)(s1 - s0));
    }
    __syncthreads();
    float a2 = bn2b[j];
    #pragma unroll
    for (int k = 0; k < DIM; k++) a2 = fmaf(gs[k], Wn2[k * H2 + j], a2);
    float g2v = fmaxf(a2, 0.f);
    outg[b * H2 + j] = g2v;
    xc[j]       = g2v;
    xc[128 + j] = t2[b * H2 + j];
    __syncthreads();
    float a4 = b4[j];
    #pragma unroll 4
    for (int k = 0; k < 256; k++) a4 = fmaf(xc[k], W4[k * H2 + j], a4);
    float y = fmaxf(a4, 0.f);
    float v = y * W5[j];
    for (int o = 16; o > 0; o >>= 1) v += __shfl_xor_sync(0xffffffffu, v, o);
    if (lane == 0) red[wid] = v;
    __syncthreads();
    if (j == 0) {
        float s = red[0] + red[1] + red[2] + red[3] + b5[0];
        out[b] = 1.f / (1.f + expf(-s));
    }
}

// ---------------- launch ----------------------------------------------------

extern "C" void kernel_launch(void* const* d_in, const int* in_sizes, int n_in,
                              void* d_out, int out_size) {
    const float* x       = (const float*)d_in[0];
    const int*   ei      = (const int*)d_in[1];
    const int*   batch   = (const int*)d_in[2];
    const float* target  = (const float*)d_in[3];
    const float* W11a = (const float*)d_in[4];   const float* b11a = (const float*)d_in[5];
    const float* W11b = (const float*)d_in[6];   const float* b11b = (const float*)d_in[7];
    const float* W12a = (const float*)d_in[8];   const float* b12a = (const float*)d_in[9];
    const float* W12b = (const float*)d_in[10];  const float* b12b = (const float*)d_in[11];
    const float* W13a = (const float*)d_in[12];  const float* b13a = (const float*)d_in[13];
    const float* W13b = (const float*)d_in[14];  const float* b13b = (const float*)d_in[15];
    const float* Wn2  = (const float*)d_in[16];  const float* bn2b = (const float*)d_in[17];
    const float* g1   = (const float*)d_in[18];  const float* be1  = (const float*)d_in[19];
    const float* W31  = (const float*)d_in[20];  const float* b31  = (const float*)d_in[21];
    const float* W32  = (const float*)d_in[22];  const float* b32  = (const float*)d_in[23];
    const float* W4   = (const float*)d_in[24];  const float* b4   = (const float*)d_in[25];
    const float* W5   = (const float*)d_in[26];  const float* b5   = (const float*)d_in[27];
    (void)in_sizes; (void)n_in; (void)out_size;

    const int* src = ei;
    const int* dst = ei + N_EDGES;

    float* out  = (float*)d_out;          // [0, 2048): sigmoid out
    float* outg = out + N_GRAPHS;         // [2048, ...): g2 [2048,128]

    void *pProj, *pHA, *pHB, *pStat, *pT1, *pT2, *pAB, *pDeg, *pAdj, *pGoff;
    cudaGetSymbolAddress(&pProj, d_proj);
    cudaGetSymbolAddress(&pHA,   d_hA);
    cudaGetSymbolAddress(&pHB,   d_hB);
    cudaGetSymbolAddress(&pStat, d_stat);
    cudaGetSymbolAddress(&pT1,   d_t1);
    cudaGetSymbolAddress(&pT2,   d_t2);
    cudaGetSymbolAddress(&pAB,   d_AB);
    cudaGetSymbolAddress(&pDeg,  d_deg);
    cudaGetSymbolAddress(&pAdj,  d_adj);
    cudaGetSymbolAddress(&pGoff, d_goff);

    float*  proj = (float*)pProj;
    float*  hA   = (float*)pHA;
    float*  hB   = (float*)pHB;
    double* stat = (double*)pStat;
    float*  t1b  = (float*)pT1;
    float*  t2b  = (float*)pT2;
    float*  ABb  = (float*)pAB;
    int*    deg  = (int*)pDeg;
    int*    adj  = (int*)pAdj;
    int*    goff = (int*)pGoff;

    const int BUILD_BLOCKS = EDGE_BLOCKS + GOFF_BLOCKS + 1 + T_DIM;

    // 1: build adjacency + goff + target BN stats + zero stats
    k_build<<<BUILD_BLOCKS, 256>>>(src, dst, deg, adj, batch, goff, target, g1, be1, ABb, stat);

    // 2: layer-1 input projection (78 -> 32)
    k_proj_in<<<PROJ_BLOCKS, 256>>>(x, W11a, proj);

    // 3: layer 1 (gather proj, W11b, elu) + piggyback t1 (front of grid)
    k_agg<1, 1><<<MLP_BLOCKS + T_BLOCKS, 256>>>(proj, deg, adj, (const double*)0,
                                                (const float*)0, b11a, W11b, b11b,
                                                hA, stat, target, ABb, W31, b31, t1b);

    // 4: layer 2 (gather hA, BN fold, W12a+W12b) + piggyback t2 (front of grid)
    k_agg<2, 2><<<MLP_BLOCKS + T_BLOCKS, 256>>>(hA, deg, adj, stat,
                                                W12a, b12a, W12b, b12b,
                                                hB, stat + 2 * DIM, t1b, ABb, W32, b32, t2b);

    // 5: layer 3 (gather hB, BN fold, W13a+W13b)
    k_agg<2, 0><<<MLP_BLOCKS, 256>>>(hB, deg, adj, stat + 2 * DIM,
                                     W13a, b13a, W13b, b13b,
                                     hA, stat + 4 * DIM, (const float*)0, (const float*)0,
                                     (const float*)0, (const float*)0, (float*)0);

    // 6: fused graph tail (inline layer-3 stats; re-zero deg for next replay)
    k_tail<<<N_GRAPHS, 128>>>(hA, stat + 4 * DIM, goff, Wn2, bn2b, t2b, W4, b4, W5, b5,
                              outg, out, deg);
}

// round 13
// speedup vs baseline: 1.4207x; 1.4207x over previous
#include <cuda_runtime.h>
#include <math.h>

#define N_NODES  100000
#define N_EDGES  1000000
#define N_GRAPHS 2048
#define F_IN     78
#define DIM      32
#define T_DIM    208
#define H1       170
#define H2       128
#define BN_EPS   1e-5f
#define DEG_CAP  64

// ---------------- scratch (device globals; no allocation allowed) ----------
__device__ float  d_proj[N_NODES * DIM];
__device__ float  d_hA[N_NODES * DIM];
__device__ float  d_hB[N_NODES * DIM];
__device__ double d_stat[3 * 2 * DIM];   // per layer: [sums(32), sumsq(32)]
__device__ float  d_t1[N_GRAPHS * H1];
__device__ float  d_t2[N_GRAPHS * H2];
__device__ float  d_AB[2 * T_DIM];
__device__ int    d_deg[N_NODES];        // zero at load; re-zeroed by k_tail
__device__ int    d_adj[N_NODES * DEG_CAP];
__device__ int    d_goff[N_GRAPHS + 1];

#define EDGE_BLOCKS  ((N_EDGES + 255) / 256)             // 3907
#define GOFF_BLOCKS  ((N_GRAPHS + 1 + 255) / 256)        // 9
#define T_BLOCKS     (N_GRAPHS / 16)                     // 128
#define MLP_BLOCKS   760                                 // +128 = 888 = 6*148 (one wave)
#define PROJ_BLOCKS  1024

// ---------------- build: adjacency + goff + target BN stats + stat zeroing
__global__ void k_build(const int* __restrict__ src, const int* __restrict__ dst,
                        int* __restrict__ deg, int* __restrict__ adj,
                        const int* __restrict__ batch, int* __restrict__ goff,
                        const float* __restrict__ target,
                        const float* __restrict__ g1, const float* __restrict__ be1,
                        float* __restrict__ AB,
                        double* __restrict__ stat) {
    int b = blockIdx.x;
    if (b < EDGE_BLOCKS) {
        int i = b * 256 + threadIdx.x;
        if (i < N_EDGES) {
            int d = dst[i];
            int c = atomicAdd(&deg[d], 1);
            if (c < DEG_CAP) adj[d * DEG_CAP + c] = src[i];
        }
        return;
    }
    if (b < EDGE_BLOCKS + GOFF_BLOCKS) {
        int g = (b - EDGE_BLOCKS) * 256 + threadIdx.x;
        if (g > N_GRAPHS) return;
        int lo = 0, hi = N_NODES;
        while (lo < hi) { int mid = (lo + hi) >> 1; if (batch[mid] < g) lo = mid + 1; else hi = mid; }
        goff[g] = lo;
        return;
    }
    if (b < EDGE_BLOCKS + GOFF_BLOCKS + 1) {
        if (threadIdx.x < 3 * 2 * DIM) stat[threadIdx.x] = 0.0;
        return;
    }
    // target BN stats: one block per column
    int c = b - EDGE_BLOCKS - GOFF_BLOCKS - 1;
    float s = 0.f, q = 0.f;
    for (int r = threadIdx.x; r < N_GRAPHS; r += blockDim.x) {
        float v = target[r * T_DIM + c];
        s += v;
        q = fmaf(v, v, q);
    }
    __shared__ float ssm[256], sqm[256];
    ssm[threadIdx.x] = s; sqm[threadIdx.x] = q;
    __syncthreads();
    for (int st = 128; st > 0; st >>= 1) {
        if (threadIdx.x < st) { ssm[threadIdx.x] += ssm[threadIdx.x + st]; sqm[threadIdx.x] += sqm[threadIdx.x + st]; }
        __syncthreads();
    }
    if (threadIdx.x == 0) {
        float m = ssm[0] / (float)N_GRAPHS;
        float v = sqm[0] / (float)N_GRAPHS - m * m;
        float inv = rsqrtf(v + BN_EPS);
        float A = g1[c] * inv;
        AB[c]         = A;
        AB[T_DIM + c] = be1[c] - m * A;
    }
}

// ---------------- node kernels ----------------------------------------------

// proj = x @ W  (x: [N,78], W: [78,32]) ; one warp per node, grid-stride
__global__ void k_proj_in(const float* __restrict__ x,
                          const float* __restrict__ W,
                          float* __restrict__ out) {
    __shared__ float Ws[F_IN * DIM];
    for (int i = threadIdx.x; i < F_IN * DIM; i += blockDim.x) Ws[i] = W[i];
    __syncthreads();
    int lane = threadIdx.x & 31;
    int gwarp = (blockIdx.x * blockDim.x + threadIdx.x) >> 5;
    const int nwarps = (PROJ_BLOCKS * 256) >> 5;
    for (int n = gwarp; n < N_NODES; n += nwarps) {
        const float* xr = x + (size_t)n * F_IN;
        float r0 = xr[lane];
        float r1 = xr[32 + lane];
        float r2 = (lane < F_IN - 64) ? xr[64 + lane] : 0.f;
        float acc = 0.f;
        #pragma unroll
        for (int k = 0; k < 32; k++)
            acc = fmaf(__shfl_sync(0xffffffffu, r0, k), Ws[k * DIM + lane], acc);
        #pragma unroll
        for (int k = 0; k < 32; k++)
            acc = fmaf(__shfl_sync(0xffffffffu, r1, k), Ws[(32 + k) * DIM + lane], acc);
        #pragma unroll
        for (int k = 0; k < F_IN - 64; k++)
            acc = fmaf(__shfl_sync(0xffffffffu, r2, k), Ws[(64 + k) * DIM + lane], acc);
        out[n * DIM + lane] = acc;
    }
}

// Target-branch blocks, W-streaming form (TP: 1=t1 GEMM, 2=t2 GEMM+softmax).
// 16 input rows staged in smem; each W element loaded ONCE and reused across
// all 16 rows in registers -> ~16x fewer LDGs than the per-row form.
template <int TP>
__device__ __forceinline__ void target_branch(int tb,
                          const float* __restrict__ tin,
                          const float* __restrict__ AB,
                          const float* __restrict__ Wt,
                          const float* __restrict__ bt,
                          float* __restrict__ tout) {
    if (TP == 1) {
        __shared__ float tn[16][T_DIM];
        const int row0 = tb * 16;
        for (int i = threadIdx.x; i < 16 * T_DIM; i += 256) {
            int r = i / T_DIM, c = i % T_DIM;
            tn[r][c] = fmaf(tin[(row0 + r) * T_DIM + c], AB[c], AB[T_DIM + c]);
        }
        __syncthreads();
        int j = threadIdx.x;
        if (j < H1) {
            float bj = bt[j];
            #pragma unroll
            for (int half = 0; half < 2; half++) {
                float acc[8];
                #pragma unroll
                for (int r = 0; r < 8; r++) acc[r] = bj;
                for (int c = 0; c < T_DIM; c++) {
                    float w = Wt[c * H1 + j];
                    #pragma unroll
                    for (int r = 0; r < 8; r++)
                        acc[r] = fmaf(tn[half * 8 + r][c], w, acc[r]);
                }
                #pragma unroll
                for (int r = 0; r < 8; r++)
                    tout[(row0 + half * 8 + r) * H1 + j] = acc[r];
            }
        }
    } else {
        __shared__ float t1s[16][H1 + 2];
        __shared__ float so[16][H2];
        const int row0 = tb * 16;
        for (int i = threadIdx.x; i < 16 * H1; i += 256) {
            int r = i / H1, c = i % H1;
            t1s[r][c] = tin[(row0 + r) * H1 + c];
        }
        __syncthreads();
        int j = threadIdx.x;
        if (j < H2) {
            float bj = bt[j];
            #pragma unroll
            for (int half = 0; half < 2; half++) {
                float acc[8];
                #pragma unroll
                for (int r = 0; r < 8; r++) acc[r] = bj;
                for (int c = 0; c < H1; c++) {
                    float w = Wt[c * H2 + j];
                    #pragma unroll
                    for (int r = 0; r < 8; r++)
                        acc[r] = fmaf(t1s[half * 8 + r][c], w, acc[r]);
                }
                #pragma unroll
                for (int r = 0; r < 8; r++)
                    so[half * 8 + r][j] = acc[r];
            }
        }
        __syncthreads();
        // softmax: each of 8 warps handles 2 rows; 4 values per lane
        int wid = threadIdx.x >> 5, lane = threadIdx.x & 31;
        #pragma unroll
        for (int rr = 0; rr < 2; rr++) {
            int r = wid * 2 + rr;
            float v0 = so[r][lane],      v1 = so[r][32 + lane];
            float v2 = so[r][64 + lane], v3 = so[r][96 + lane];
            float m = fmaxf(fmaxf(v0, v1), fmaxf(v2, v3));
            #pragma unroll
            for (int o = 16; o > 0; o >>= 1)
                m = fmaxf(m, __shfl_xor_sync(0xffffffffu, m, o));
            float e0 = expf(v0 - m), e1 = expf(v1 - m);
            float e2 = expf(v2 - m), e3 = expf(v3 - m);
            float s = (e0 + e1) + (e2 + e3);
            #pragma unroll
            for (int o = 16; o > 0; o >>= 1)
                s += __shfl_xor_sync(0xffffffffu, s, o);
            float inv = 1.f / s;
            tout[(row0 + r) * H2 + lane]      = e0 * inv;
            tout[(row0 + r) * H2 + 32 + lane] = e1 * inv;
            tout[(row0 + r) * H2 + 64 + lane] = e2 * inv;
            tout[(row0 + r) * H2 + 96 + lane] = e3 * inv;
        }
    }
}

// 8-way batched gather: issue 8 independent LDGs per batch, then reduce.
__device__ __forceinline__ float gather8(const float* __restrict__ base,
                                         int idx, int cnt, int lane) {
    float a0 = 0.f, a1 = 0.f, a2 = 0.f, a3 = 0.f;
    int k = 0;
    for (; k + 8 <= cnt; k += 8) {
        int s0 = __shfl_sync(0xffffffffu, idx, k);
        int s1 = __shfl_sync(0xffffffffu, idx, k + 1);
        int s2 = __shfl_sync(0xffffffffu, idx, k + 2);
        int s3 = __shfl_sync(0xffffffffu, idx, k + 3);
        int s4 = __shfl_sync(0xffffffffu, idx, k + 4);
        int s5 = __shfl_sync(0xffffffffu, idx, k + 5);
        int s6 = __shfl_sync(0xffffffffu, idx, k + 6);
        int s7 = __shfl_sync(0xffffffffu, idx, k + 7);
        float t0 = base[s0 * DIM + lane];
        float t1 = base[s1 * DIM + lane];
        float t2 = base[s2 * DIM + lane];
        float t3 = base[s3 * DIM + lane];
        float t4 = base[s4 * DIM + lane];
        float t5 = base[s5 * DIM + lane];
        float t6 = base[s6 * DIM + lane];
        float t7 = base[s7 * DIM + lane];
        a0 += t0; a1 += t1; a2 += t2; a3 += t3;
        a0 += t4; a1 += t5; a2 += t6; a3 += t7;
    }
    if (k + 4 <= cnt) {
        int s0 = __shfl_sync(0xffffffffu, idx, k);
        int s1 = __shfl_sync(0xffffffffu, idx, k + 1);
        int s2 = __shfl_sync(0xffffffffu, idx, k + 2);
        int s3 = __shfl_sync(0xffffffffu, idx, k + 3);
        float t0 = base[s0 * DIM + lane];
        float t1 = base[s1 * DIM + lane];
        float t2 = base[s2 * DIM + lane];
        float t3 = base[s3 * DIM + lane];
        a0 += t0; a1 += t1; a2 += t2; a3 += t3;
        k += 4;
    }
    if (k + 2 <= cnt) {
        int s0 = __shfl_sync(0xffffffffu, idx, k);
        int s1 = __shfl_sync(0xffffffffu, idx, k + 1);
        float t0 = base[s0 * DIM + lane];
        float t1 = base[s1 * DIM + lane];
        a0 += t0; a1 += t1;
        k += 2;
    }
    if (k < cnt)
        a0 += base[__shfl_sync(0xffffffffu, idx, k) * DIM + lane];
    return (a0 + a1) + (a2 + a3);
}

// Fused GIN layer, 4 nodes per warp / float4 per lane (8 lanes per node).
// NMAT=1 (layer 1): z = relu(gather(proj)+b1); out = elu(z@W2 + b2)
// NMAT=2 (layers 2/3): z = gather(h); r = relu(z@W1f + (1+deg)*badd + b1);
//                      out = relu(r@W2 + b2).  W1f = diag(sc)@W1 (BN fold).
template <int NMAT, int TP>
__global__ void __launch_bounds__(256, 6)
k_agg(const float* __restrict__ hin,
      const int* __restrict__ deg,
      const int* __restrict__ adj,
      const double* __restrict__ statp,
      const float* __restrict__ W1,
      const float* __restrict__ b1,
      const float* __restrict__ W2,
      const float* __restrict__ b2,
      float* __restrict__ hout,
      double* __restrict__ stat,
      const float* __restrict__ tin,
      const float* __restrict__ AB,
      const float* __restrict__ Wt,
      const float* __restrict__ bt,
      float* __restrict__ tout) {
    if (TP != 0 && blockIdx.x < T_BLOCKS) {
        target_branch<TP>(blockIdx.x, tin, AB, Wt, bt, tout);
        return;
    }
    const int abid = (TP != 0) ? (blockIdx.x - T_BLOCKS) : blockIdx.x;

    __shared__ float4 W1q[DIM][8];
    __shared__ float4 W2q[DIM][8];
    __shared__ float4 baddq[8], b1q[8], b2q[8];
    __shared__ float  red[2 * DIM];

    float* W1f   = (float*)W1q;
    float* W2f   = (float*)W2q;
    float* badds = (float*)baddq;
    float* b1s   = (float*)b1q;
    float* b2s   = (float*)b2q;
    const int tid = threadIdx.x;

    if (tid < 32) {
        int j = tid;
        if (NMAT == 2) {
            double m = statp[j] * (1.0 / N_NODES);
            double v = statp[DIM + j] * (1.0 / N_NODES) - m * m;
            float sc = (float)(1.0 / sqrt(v + (double)BN_EPS));
            float sh = (float)(-m) * sc;
            float bacc = 0.f;
            #pragma unroll
            for (int k = 0; k < DIM; k++) {
                float w = W1[k * DIM + j];
                W1f[k * DIM + j] = __shfl_sync(0xffffffffu, sc, k) * w;
                bacc = fmaf(__shfl_sync(0xffffffffu, sh, k), w, bacc);
            }
            badds[j] = bacc;
        }
        b1s[j] = b1[j];
        b2s[j] = b2[j];
    }
    for (int i = tid; i < DIM * DIM; i += 256) W2f[i] = W2[i];
    if (tid < 2 * DIM) red[tid] = 0.f;
    __syncthreads();

    const int lane = tid & 31;
    const int g    = lane >> 3;    // node group 0..3
    const int sl   = lane & 7;     // feature quad 0..7
    const int gb   = g << 3;
    const int gwarp = (abid * 256 + tid) >> 5;
    const int stride4 = (MLP_BLOCKS * 8) * 4;
    float4 lsum = make_float4(0.f, 0.f, 0.f, 0.f);
    float4 lsq  = make_float4(0.f, 0.f, 0.f, 0.f);

    for (int n4 = gwarp * 4; n4 < N_NODES; n4 += stride4) {
        const int n = n4 + g;
        const int dT = deg[n];
        int dn = dT > DEG_CAP ? DEG_CAP : dT;
        const int* an = adj + (size_t)n * DEG_CAP;

        float4 z = *(const float4*)(hin + (size_t)n * DIM + sl * 4);

        int dmax = dn;
        #pragma unroll
        for (int o = 16; o > 0; o >>= 1) {
            int v = __shfl_xor_sync(0xffffffffu, dmax, o);
            dmax = dmax > v ? dmax : v;
        }
        for (int base = 0; base < dmax; base += 8) {
            int idx = (base + sl < dn) ? an[base + sl] : -1;
            int mw = dmax - base; if (mw > 8) mw = 8;
            #pragma unroll 4
            for (int k = 0; k < mw; k++) {
                int s = __shfl_sync(0xffffffffu, idx, gb + k);
                bool valid = (s >= 0);
                int ss = valid ? s : 0;
                float4 t = *(const float4*)(hin + (size_t)ss * DIM + sl * 4);
                float mk = valid ? 1.f : 0.f;
                z.x = fmaf(mk, t.x, z.x);
                z.y = fmaf(mk, t.y, z.y);
                z.z = fmaf(mk, t.z, z.z);
                z.w = fmaf(mk, t.w, z.w);
            }
        }

        if (NMAT == 1) {
            float4 bb1 = b1q[sl];
            z.x = fmaxf(z.x + bb1.x, 0.f);
            z.y = fmaxf(z.y + bb1.y, 0.f);
            z.z = fmaxf(z.z + bb1.z, 0.f);
            z.w = fmaxf(z.w + bb1.w, 0.f);
        } else {
            // matvec1: acc1 = z @ W1f + (1+deg)*badd + b1 ; z := relu(acc1)
            float df = (float)(1 + dT);
            float4 bd  = baddq[sl];
            float4 bb1 = b1q[sl];
            float4 a;
            a.x = fmaf(df, bd.x, bb1.x);
            a.y = fmaf(df, bd.y, bb1.y);
            a.z = fmaf(df, bd.z, bb1.z);
            a.w = fmaf(df, bd.w, bb1.w);
            #pragma unroll
            for (int kq = 0; kq < 8; kq++) {
                float zx = __shfl_sync(0xffffffffu, z.x, gb + kq);
                float zy = __shfl_sync(0xffffffffu, z.y, gb + kq);
                float zz = __shfl_sync(0xffffffffu, z.z, gb + kq);
                float zw = __shfl_sync(0xffffffffu, z.w, gb + kq);
                float4 w;
                w = W1q[4 * kq + 0][sl];
                a.x = fmaf(zx, w.x, a.x); a.y = fmaf(zx, w.y, a.y);
                a.z = fmaf(zx, w.z, a.z); a.w = fmaf(zx, w.w, a.w);
                w = W1q[4 * kq + 1][sl];
                a.x = fmaf(zy, w.x, a.x); a.y = fmaf(zy, w.y, a.y);
                a.z = fmaf(zy, w.z, a.z); a.w = fmaf(zy, w.w, a.w);
                w = W1q[4 * kq + 2][sl];
                a.x = fmaf(zz, w.x, a.x); a.y = fmaf(zz, w.y, a.y);
                a.z = fmaf(zz, w.z, a.z); a.w = fmaf(zz, w.w, a.w);
                w = W1q[4 * kq + 3][sl];
                a.x = fmaf(zw, w.x, a.x); a.y = fmaf(zw, w.y, a.y);
                a.z = fmaf(zw, w.z, a.z); a.w = fmaf(zw, w.w, a.w);
            }
            z.x = fmaxf(a.x, 0.f);
            z.y = fmaxf(a.y, 0.f);
            z.z = fmaxf(a.z, 0.f);
            z.w = fmaxf(a.w, 0.f);
        }

        // matvec2: out = z @ W2 + b2
        float4 o = b2q[sl];
        #pragma unroll
        for (int kq = 0; kq < 8; kq++) {
            float zx = __shfl_sync(0xffffffffu, z.x, gb + kq);
            float zy = __shfl_sync(0xffffffffu, z.y, gb + kq);
            float zz = __shfl_sync(0xffffffffu, z.z, gb + kq);
            float zw = __shfl_sync(0xffffffffu, z.w, gb + kq);
            float4 w;
            w = W2q[4 * kq + 0][sl];
            o.x = fmaf(zx, w.x, o.x); o.y = fmaf(zx, w.y, o.y);
            o.z = fmaf(zx, w.z, o.z); o.w = fmaf(zx, w.w, o.w);
            w = W2q[4 * kq + 1][sl];
            o.x = fmaf(zy, w.x, o.x); o.y = fmaf(zy, w.y, o.y);
            o.z = fmaf(zy, w.z, o.z); o.w = fmaf(zy, w.w, o.w);
            w = W2q[4 * kq + 2][sl];
            o.x = fmaf(zz, w.x, o.x); o.y = fmaf(zz, w.y, o.y);
            o.z = fmaf(zz, w.z, o.z); o.w = fmaf(zz, w.w, o.w);
            w = W2q[4 * kq + 3][sl];
            o.x = fmaf(zw, w.x, o.x); o.y = fmaf(zw, w.y, o.y);
            o.z = fmaf(zw, w.z, o.z); o.w = fmaf(zw, w.w, o.w);
        }
        if (NMAT == 1) {
            o.x = (o.x > 0.f) ? o.x : expm1f(o.x);
            o.y = (o.y > 0.f) ? o.y : expm1f(o.y);
            o.z = (o.z > 0.f) ? o.z : expm1f(o.z);
            o.w = (o.w > 0.f) ? o.w : expm1f(o.w);
        } else {
            o.x = fmaxf(o.x, 0.f);
            o.y = fmaxf(o.y, 0.f);
            o.z = fmaxf(o.z, 0.f);
            o.w = fmaxf(o.w, 0.f);
        }
        *(float4*)(hout + (size_t)n * DIM + sl * 4) = o;
        lsum.x += o.x; lsq.x = fmaf(o.x, o.x, lsq.x);
        lsum.y += o.y; lsq.y = fmaf(o.y, o.y, lsq.y);
        lsum.z += o.z; lsq.z = fmaf(o.z, o.z, lsq.z);
        lsum.w += o.w; lsq.w = fmaf(o.w, o.w, lsq.w);
    }

    atomicAdd(&red[4 * sl + 0], lsum.x);
    atomicAdd(&red[4 * sl + 1], lsum.y);
    atomicAdd(&red[4 * sl + 2], lsum.z);
    atomicAdd(&red[4 * sl + 3], lsum.w);
    atomicAdd(&red[DIM + 4 * sl + 0], lsq.x);
    atomicAdd(&red[DIM + 4 * sl + 1], lsq.y);
    atomicAdd(&red[DIM + 4 * sl + 2], lsq.z);
    atomicAdd(&red[DIM + 4 * sl + 3], lsq.w);
    __syncthreads();
    if (tid < 2 * DIM)
        atomicAdd(&stat[tid], (double)red[tid]);
}

// Fused graph tail: inline layer-3 BN stats + pool + g2 + head; also re-zeroes deg.
__global__ void k_tail(const float* __restrict__ h,
                       const double* __restrict__ statp,
                       const int* __restrict__ goff,
                       const float* __restrict__ Wn2, const float* __restrict__ bn2b,
                       const float* __restrict__ t2,
                       const float* __restrict__ W4, const float* __restrict__ b4,
                       const float* __restrict__ W5, const float* __restrict__ b5,
                       float* __restrict__ outg,
                       float* __restrict__ out,
                       int* __restrict__ deg) {
    __shared__ float ss_s[2 * DIM];
    __shared__ float pacc[4][DIM];
    __shared__ float gs[DIM];
    __shared__ float xc[256];
    __shared__ float red[4];
    int b = blockIdx.x;
    int j = threadIdx.x;
    int wid = j >> 5, lane = j & 31;
    int zi = b * 128 + j;
    if (zi < N_NODES) deg[zi] = 0;
    if (j < 32) {
        double m = statp[j] * (1.0 / N_NODES);
        double v = statp[DIM + j] * (1.0 / N_NODES) - m * m;
        float sc = (float)(1.0 / sqrt(v + (double)BN_EPS));
        ss_s[j]       = sc;
        ss_s[DIM + j] = (float)(-m) * sc;
    }
    __syncthreads();
    int s0 = goff[b], s1 = goff[b + 1];
    float acc = 0.f;
    for (int n = s0 + wid; n < s1; n += 4) acc += h[n * DIM + lane];
    pacc[wid][lane] = acc;
    __syncthreads();
    if (wid == 0) {
        float a = pacc[0][lane] + pacc[1][lane] + pacc[2][lane] + pacc[3][lane];
        gs[lane] = fmaf(ss_s[lane], a, ss_s[DIM + lane] * (float)(s1 - s0));
    }
    __syncthreads();
    float a2 = bn2b[j];
    #pragma unroll
    for (int k = 0; k < DIM; k++) a2 = fmaf(gs[k], Wn2[k * H2 + j], a2);
    float g2v = fmaxf(a2, 0.f);
    outg[b * H2 + j] = g2v;
    xc[j]       = g2v;
    xc[128 + j] = t2[b * H2 + j];
    __syncthreads();
    float a4 = b4[j];
    #pragma unroll 4
    for (int k = 0; k < 256; k++) a4 = fmaf(xc[k], W4[k * H2 + j], a4);
    float y = fmaxf(a4, 0.f);
    float v = y * W5[j];
    for (int o = 16; o > 0; o >>= 1) v += __shfl_xor_sync(0xffffffffu, v, o);
    if (lane == 0) red[wid] = v;
    __syncthreads();
    if (j == 0) {
        float s = red[0] + red[1] + red[2] + red[3] + b5[0];
        out[b] = 1.f / (1.f + expf(-s));
    }
}

// ---------------- launch ----------------------------------------------------

extern "C" void kernel_launch(void* const* d_in, const int* in_sizes, int n_in,
                              void* d_out, int out_size) {
    const float* x       = (const float*)d_in[0];
    const int*   ei      = (const int*)d_in[1];
    const int*   batch   = (const int*)d_in[2];
    const float* target  = (const float*)d_in[3];
    const float* W11a = (const float*)d_in[4];   const float* b11a = (const float*)d_in[5];
    const float* W11b = (const float*)d_in[6];   const float* b11b = (const float*)d_in[7];
    const float* W12a = (const float*)d_in[8];   const float* b12a = (const float*)d_in[9];
    const float* W12b = (const float*)d_in[10];  const float* b12b = (const float*)d_in[11];
    const float* W13a = (const float*)d_in[12];  const float* b13a = (const float*)d_in[13];
    const float* W13b = (const float*)d_in[14];  const float* b13b = (const float*)d_in[15];
    const float* Wn2  = (const float*)d_in[16];  const float* bn2b = (const float*)d_in[17];
    const float* g1   = (const float*)d_in[18];  const float* be1  = (const float*)d_in[19];
    const float* W31  = (const float*)d_in[20];  const float* b31  = (const float*)d_in[21];
    const float* W32  = (const float*)d_in[22];  const float* b32  = (const float*)d_in[23];
    const float* W4   = (const float*)d_in[24];  const float* b4   = (const float*)d_in[25];
    const float* W5   = (const float*)d_in[26];  const float* b5   = (const float*)d_in[27];
    (void)in_sizes; (void)n_in; (void)out_size;

    const int* src = ei;
    const int* dst = ei + N_EDGES;

    float* out  = (float*)d_out;          // [0, 2048): sigmoid out
    float* outg = out + N_GRAPHS;         // [2048, ...): g2 [2048,128]

    void *pProj, *pHA, *pHB, *pStat, *pT1, *pT2, *pAB, *pDeg, *pAdj, *pGoff;
    cudaGetSymbolAddress(&pProj, d_proj);
    cudaGetSymbolAddress(&pHA,   d_hA);
    cudaGetSymbolAddress(&pHB,   d_hB);
    cudaGetSymbolAddress(&pStat, d_stat);
    cudaGetSymbolAddress(&pT1,   d_t1);
    cudaGetSymbolAddress(&pT2,   d_t2);
    cudaGetSymbolAddress(&pAB,   d_AB);
    cudaGetSymbolAddress(&pDeg,  d_deg);
    cudaGetSymbolAddress(&pAdj,  d_adj);
    cudaGetSymbolAddress(&pGoff, d_goff);

    float*  proj = (float*)pProj;
    float*  hA   = (float*)pHA;
    float*  hB   = (float*)pHB;
    double* stat = (double*)pStat;
    float*  t1b  = (float*)pT1;
    float*  t2b  = (float*)pT2;
    float*  ABb  = (float*)pAB;
    int*    deg  = (int*)pDeg;
    int*    adj  = (int*)pAdj;
    int*    goff = (int*)pGoff;

    const int BUILD_BLOCKS = EDGE_BLOCKS + GOFF_BLOCKS + 1 + T_DIM;

    // 1: build adjacency + goff + target BN stats + zero stats
    k_build<<<BUILD_BLOCKS, 256>>>(src, dst, deg, adj, batch, goff, target, g1, be1, ABb, stat);

    // 2: layer-1 input projection (78 -> 32)
    k_proj_in<<<PROJ_BLOCKS, 256>>>(x, W11a, proj);

    // 3: layer 1 (gather proj, W11b, elu) + piggyback t1 (front of grid)
    k_agg<1, 1><<<MLP_BLOCKS + T_BLOCKS, 256>>>(proj, deg, adj, (const double*)0,
                                                (const float*)0, b11a, W11b, b11b,
                                                hA, stat, target, ABb, W31, b31, t1b);

    // 4: layer 2 (gather hA, BN fold, W12a+W12b) + piggyback t2 (front of grid)
    k_agg<2, 2><<<MLP_BLOCKS + T_BLOCKS, 256>>>(hA, deg, adj, stat,
                                                W12a, b12a, W12b, b12b,
                                                hB, stat + 2 * DIM, t1b, ABb, W32, b32, t2b);

    // 5: layer 3 (gather hB, BN fold, W13a+W13b)
    k_agg<2, 0><<<MLP_BLOCKS, 256>>>(hB, deg, adj, stat + 2 * DIM,
                                     W13a, b13a, W13b, b13b,
                                     hA, stat + 4 * DIM, (const float*)0, (const float*)0,
                                     (const float*)0, (const float*)0, (float*)0);

    // 6: fused graph tail (inline layer-3 stats; re-zero deg for next replay)
    k_tail<<<N_GRAPHS, 128>>>(hA, stat + 4 * DIM, goff, Wn2, bn2b, t2b, W4, b4, W5, b5,
                              outg, out, deg);
}

// round 14
// speedup vs baseline: 1.4389x; 1.0128x over previous
#include <cuda_runtime.h>
#include <math.h>

#define N_NODES  100000
#define N_EDGES  1000000
#define N_GRAPHS 2048
#define F_IN     78
#define DIM      32
#define T_DIM    208
#define H1       170
#define H2       128
#define BN_EPS   1e-5f
#define DEG_CAP  64

// ---------------- scratch (device globals; no allocation allowed) ----------
__device__ float  d_proj[N_NODES * DIM];
__device__ float  d_hA[N_NODES * DIM];
__device__ float  d_hB[N_NODES * DIM];
__device__ double d_stat[3 * 2 * DIM];   // per layer: [sums(32), sumsq(32)]
__device__ float  d_t1[N_GRAPHS * H1];
__device__ float  d_t2[N_GRAPHS * H2];
__device__ float  d_AB[2 * T_DIM];
__device__ int    d_deg[N_NODES];        // zero at load; re-zeroed by k_tail
__device__ int    d_adj[N_NODES * DEG_CAP];
__device__ int    d_goff[N_GRAPHS + 1];

#define EDGE_BLOCKS  ((N_EDGES + 255) / 256)             // 3907
#define GOFF_BLOCKS  ((N_GRAPHS + 1 + 255) / 256)        // 9
#define T_BLOCKS     (N_GRAPHS / 16)                     // 128
#define MLP_BLOCKS   760                                 // +128 = 888 = 6*148 (one wave)
#define PROJ_BLOCKS  1024

// ---------------- build: adjacency + goff + target BN stats + stat zeroing
__global__ void k_build(const int* __restrict__ src, const int* __restrict__ dst,
                        int* __restrict__ deg, int* __restrict__ adj,
                        const int* __restrict__ batch, int* __restrict__ goff,
                        const float* __restrict__ target,
                        const float* __restrict__ g1, const float* __restrict__ be1,
                        float* __restrict__ AB,
                        double* __restrict__ stat) {
    int b = blockIdx.x;
    if (b < EDGE_BLOCKS) {
        int i = b * 256 + threadIdx.x;
        if (i < N_EDGES) {
            int d = dst[i];
            int c = atomicAdd(&deg[d], 1);
            if (c < DEG_CAP) adj[d * DEG_CAP + c] = src[i];
        }
        return;
    }
    if (b < EDGE_BLOCKS + GOFF_BLOCKS) {
        int g = (b - EDGE_BLOCKS) * 256 + threadIdx.x;
        if (g > N_GRAPHS) return;
        int lo = 0, hi = N_NODES;
        while (lo < hi) { int mid = (lo + hi) >> 1; if (batch[mid] < g) lo = mid + 1; else hi = mid; }
        goff[g] = lo;
        return;
    }
    if (b < EDGE_BLOCKS + GOFF_BLOCKS + 1) {
        if (threadIdx.x < 3 * 2 * DIM) stat[threadIdx.x] = 0.0;
        return;
    }
    // target BN stats: one block per column
    int c = b - EDGE_BLOCKS - GOFF_BLOCKS - 1;
    float s = 0.f, q = 0.f;
    for (int r = threadIdx.x; r < N_GRAPHS; r += blockDim.x) {
        float v = target[r * T_DIM + c];
        s += v;
        q = fmaf(v, v, q);
    }
    __shared__ float ssm[256], sqm[256];
    ssm[threadIdx.x] = s; sqm[threadIdx.x] = q;
    __syncthreads();
    for (int st = 128; st > 0; st >>= 1) {
        if (threadIdx.x < st) { ssm[threadIdx.x] += ssm[threadIdx.x + st]; sqm[threadIdx.x] += sqm[threadIdx.x + st]; }
        __syncthreads();
    }
    if (threadIdx.x == 0) {
        float m = ssm[0] / (float)N_GRAPHS;
        float v = sqm[0] / (float)N_GRAPHS - m * m;
        float inv = rsqrtf(v + BN_EPS);
        float A = g1[c] * inv;
        AB[c]         = A;
        AB[T_DIM + c] = be1[c] - m * A;
    }
}

// ---------------- node kernels ----------------------------------------------

// proj = x @ W  (x: [N,78], W: [78,32]) ; one warp per node, grid-stride
__global__ void k_proj_in(const float* __restrict__ x,
                          const float* __restrict__ W,
                          float* __restrict__ out) {
    __shared__ float Ws[F_IN * DIM];
    for (int i = threadIdx.x; i < F_IN * DIM; i += blockDim.x) Ws[i] = W[i];
    __syncthreads();
    int lane = threadIdx.x & 31;
    int gwarp = (blockIdx.x * blockDim.x + threadIdx.x) >> 5;
    const int nwarps = (PROJ_BLOCKS * 256) >> 5;
    for (int n = gwarp; n < N_NODES; n += nwarps) {
        const float* xr = x + (size_t)n * F_IN;
        float r0 = xr[lane];
        float r1 = xr[32 + lane];
        float r2 = (lane < F_IN - 64) ? xr[64 + lane] : 0.f;
        float acc = 0.f;
        #pragma unroll
        for (int k = 0; k < 32; k++)
            acc = fmaf(__shfl_sync(0xffffffffu, r0, k), Ws[k * DIM + lane], acc);
        #pragma unroll
        for (int k = 0; k < 32; k++)
            acc = fmaf(__shfl_sync(0xffffffffu, r1, k), Ws[(32 + k) * DIM + lane], acc);
        #pragma unroll
        for (int k = 0; k < F_IN - 64; k++)
            acc = fmaf(__shfl_sync(0xffffffffu, r2, k), Ws[(64 + k) * DIM + lane], acc);
        out[n * DIM + lane] = acc;
    }
}

// Target-branch blocks, W-streaming form (TP: 1=t1 GEMM, 2=t2 GEMM+softmax).
// 16 input rows staged in smem; each W element loaded ONCE and reused across
// all 16 rows in registers -> ~16x fewer LDGs than the per-row form.
template <int TP>
__device__ __forceinline__ void target_branch(int tb,
                          const float* __restrict__ tin,
                          const float* __restrict__ AB,
                          const float* __restrict__ Wt,
                          const float* __restrict__ bt,
                          float* __restrict__ tout) {
    if (TP == 1) {
        __shared__ float tn[16][T_DIM];
        const int row0 = tb * 16;
        for (int i = threadIdx.x; i < 16 * T_DIM; i += 256) {
            int r = i / T_DIM, c = i % T_DIM;
            tn[r][c] = fmaf(tin[(row0 + r) * T_DIM + c], AB[c], AB[T_DIM + c]);
        }
        __syncthreads();
        int j = threadIdx.x;
        if (j < H1) {
            float bj = bt[j];
            #pragma unroll
            for (int half = 0; half < 2; half++) {
                float acc[8];
                #pragma unroll
                for (int r = 0; r < 8; r++) acc[r] = bj;
                for (int c = 0; c < T_DIM; c++) {
                    float w = Wt[c * H1 + j];
                    #pragma unroll
                    for (int r = 0; r < 8; r++)
                        acc[r] = fmaf(tn[half * 8 + r][c], w, acc[r]);
                }
                #pragma unroll
                for (int r = 0; r < 8; r++)
                    tout[(row0 + half * 8 + r) * H1 + j] = acc[r];
            }
        }
    } else {
        __shared__ float t1s[16][H1 + 2];
        __shared__ float so[16][H2];
        const int row0 = tb * 16;
        for (int i = threadIdx.x; i < 16 * H1; i += 256) {
            int r = i / H1, c = i % H1;
            t1s[r][c] = tin[(row0 + r) * H1 + c];
        }
        __syncthreads();
        int j = threadIdx.x;
        if (j < H2) {
            float bj = bt[j];
            #pragma unroll
            for (int half = 0; half < 2; half++) {
                float acc[8];
                #pragma unroll
                for (int r = 0; r < 8; r++) acc[r] = bj;
                for (int c = 0; c < H1; c++) {
                    float w = Wt[c * H2 + j];
                    #pragma unroll
                    for (int r = 0; r < 8; r++)
                        acc[r] = fmaf(t1s[half * 8 + r][c], w, acc[r]);
                }
                #pragma unroll
                for (int r = 0; r < 8; r++)
                    so[half * 8 + r][j] = acc[r];
            }
        }
        __syncthreads();
        // softmax: each of 8 warps handles 2 rows; 4 values per lane
        int wid = threadIdx.x >> 5, lane = threadIdx.x & 31;
        #pragma unroll
        for (int rr = 0; rr < 2; rr++) {
            int r = wid * 2 + rr;
            float v0 = so[r][lane],      v1 = so[r][32 + lane];
            float v2 = so[r][64 + lane], v3 = so[r][96 + lane];
            float m = fmaxf(fmaxf(v0, v1), fmaxf(v2, v3));
            #pragma unroll
            for (int o = 16; o > 0; o >>= 1)
                m = fmaxf(m, __shfl_xor_sync(0xffffffffu, m, o));
            float e0 = expf(v0 - m), e1 = expf(v1 - m);
            float e2 = expf(v2 - m), e3 = expf(v3 - m);
            float s = (e0 + e1) + (e2 + e3);
            #pragma unroll
            for (int o = 16; o > 0; o >>= 1)
                s += __shfl_xor_sync(0xffffffffu, s, o);
            float inv = 1.f / s;
            tout[(row0 + r) * H2 + lane]      = e0 * inv;
            tout[(row0 + r) * H2 + 32 + lane] = e1 * inv;
            tout[(row0 + r) * H2 + 64 + lane] = e2 * inv;
            tout[(row0 + r) * H2 + 96 + lane] = e3 * inv;
        }
    }
}

// Fused GIN layer, 4 nodes per warp / float4 per lane (8 lanes per node).
// Gather: per-group loop to OWN degree; indices from int4 broadcast loads
// (no SHFL in the address path, no masked garbage loads in full batches).
// NMAT=1 (layer 1): z = relu(gather(proj)+b1); out = elu(z@W2 + b2)
// NMAT=2 (layers 2/3): z = gather(h); r = relu(z@W1f + (1+deg)*badd + b1);
//                      out = relu(r@W2 + b2).  W1f = diag(sc)@W1 (BN fold).
template <int NMAT, int TP>
__global__ void __launch_bounds__(256, 6)
k_agg(const float* __restrict__ hin,
      const int* __restrict__ deg,
      const int* __restrict__ adj,
      const double* __restrict__ statp,
      const float* __restrict__ W1,
      const float* __restrict__ b1,
      const float* __restrict__ W2,
      const float* __restrict__ b2,
      float* __restrict__ hout,
      double* __restrict__ stat,
      const float* __restrict__ tin,
      const float* __restrict__ AB,
      const float* __restrict__ Wt,
      const float* __restrict__ bt,
      float* __restrict__ tout) {
    if (TP != 0 && blockIdx.x < T_BLOCKS) {
        target_branch<TP>(blockIdx.x, tin, AB, Wt, bt, tout);
        return;
    }
    const int abid = (TP != 0) ? (blockIdx.x - T_BLOCKS) : blockIdx.x;

    __shared__ float4 W1q[DIM][8];
    __shared__ float4 W2q[DIM][8];
    __shared__ float4 baddq[8], b1q[8], b2q[8];
    __shared__ float  red[2 * DIM];

    float* W1f   = (float*)W1q;
    float* W2f   = (float*)W2q;
    float* badds = (float*)baddq;
    float* b1s   = (float*)b1q;
    float* b2s   = (float*)b2q;
    const int tid = threadIdx.x;

    if (tid < 32) {
        int j = tid;
        if (NMAT == 2) {
            double m = statp[j] * (1.0 / N_NODES);
            double v = statp[DIM + j] * (1.0 / N_NODES) - m * m;
            float sc = (float)(1.0 / sqrt(v + (double)BN_EPS));
            float sh = (float)(-m) * sc;
            float bacc = 0.f;
            #pragma unroll
            for (int k = 0; k < DIM; k++) {
                float w = W1[k * DIM + j];
                W1f[k * DIM + j] = __shfl_sync(0xffffffffu, sc, k) * w;
                bacc = fmaf(__shfl_sync(0xffffffffu, sh, k), w, bacc);
            }
            badds[j] = bacc;
        }
        b1s[j] = b1[j];
        b2s[j] = b2[j];
    }
    for (int i = tid; i < DIM * DIM; i += 256) W2f[i] = W2[i];
    if (tid < 2 * DIM) red[tid] = 0.f;
    __syncthreads();

    const int lane = tid & 31;
    const int g    = lane >> 3;    // node group 0..3
    const int sl   = lane & 7;     // feature quad 0..7
    const int gb   = g << 3;
    const int gwarp = (abid * 256 + tid) >> 5;
    const int stride4 = (MLP_BLOCKS * 8) * 4;
    float4 lsum = make_float4(0.f, 0.f, 0.f, 0.f);
    float4 lsq  = make_float4(0.f, 0.f, 0.f, 0.f);

    for (int n4 = gwarp * 4; n4 < N_NODES; n4 += stride4) {
        const int n = n4 + g;
        const int dT = deg[n];
        int dn = dT > DEG_CAP ? DEG_CAP : dT;
        const int* an = adj + (size_t)n * DEG_CAP;

        float4 z = *(const float4*)(hin + (size_t)n * DIM + sl * 4);

        // Per-group gather: int4 broadcast index loads, zero SHFLs in the
        // address path; full batches issue 8 independent unmasked LDG.128s.
        for (int base = 0; base < dn; base += 8) {
            int4 i0 = *(const int4*)(an + base);
            int4 i1 = *(const int4*)(an + base + 4);
            int rem = dn - base;
            if (rem >= 8) {
                float4 t0 = *(const float4*)(hin + (size_t)i0.x * DIM + sl * 4);
                float4 t1 = *(const float4*)(hin + (size_t)i0.y * DIM + sl * 4);
                float4 t2 = *(const float4*)(hin + (size_t)i0.z * DIM + sl * 4);
                float4 t3 = *(const float4*)(hin + (size_t)i0.w * DIM + sl * 4);
                float4 t4 = *(const float4*)(hin + (size_t)i1.x * DIM + sl * 4);
                float4 t5 = *(const float4*)(hin + (size_t)i1.y * DIM + sl * 4);
                float4 t6 = *(const float4*)(hin + (size_t)i1.z * DIM + sl * 4);
                float4 t7 = *(const float4*)(hin + (size_t)i1.w * DIM + sl * 4);
                z.x += ((t0.x + t1.x) + (t2.x + t3.x)) + ((t4.x + t5.x) + (t6.x + t7.x));
                z.y += ((t0.y + t1.y) + (t2.y + t3.y)) + ((t4.y + t5.y) + (t6.y + t7.y));
                z.z += ((t0.z + t1.z) + (t2.z + t3.z)) + ((t4.z + t5.z) + (t6.z + t7.z));
                z.w += ((t0.w + t1.w) + (t2.w + t3.w)) + ((t4.w + t5.w) + (t6.w + t7.w));
            } else {
                #pragma unroll
                for (int k = 0; k < 7; k++) {
                    if (k < rem) {
                        int s = (k < 4) ? ((const int*)&i0)[k] : ((const int*)&i1)[k - 4];
                        float4 t = *(const float4*)(hin + (size_t)s * DIM + sl * 4);
                        z.x += t.x; z.y += t.y; z.z += t.z; z.w += t.w;
                    }
                }
            }
        }

        if (NMAT == 1) {
            float4 bb1 = b1q[sl];
            z.x = fmaxf(z.x + bb1.x, 0.f);
            z.y = fmaxf(z.y + bb1.y, 0.f);
            z.z = fmaxf(z.z + bb1.z, 0.f);
            z.w = fmaxf(z.w + bb1.w, 0.f);
        } else {
            // matvec1: acc1 = z @ W1f + (1+deg)*badd + b1 ; z := relu(acc1)
            float df = (float)(1 + dT);
            float4 bd  = baddq[sl];
            float4 bb1 = b1q[sl];
            float4 a;
            a.x = fmaf(df, bd.x, bb1.x);
            a.y = fmaf(df, bd.y, bb1.y);
            a.z = fmaf(df, bd.z, bb1.z);
            a.w = fmaf(df, bd.w, bb1.w);
            #pragma unroll
            for (int kq = 0; kq < 8; kq++) {
                float zx = __shfl_sync(0xffffffffu, z.x, gb + kq);
                float zy = __shfl_sync(0xffffffffu, z.y, gb + kq);
                float zz = __shfl_sync(0xffffffffu, z.z, gb + kq);
                float zw = __shfl_sync(0xffffffffu, z.w, gb + kq);
                float4 w;
                w = W1q[4 * kq + 0][sl];
                a.x = fmaf(zx, w.x, a.x); a.y = fmaf(zx, w.y, a.y);
                a.z = fmaf(zx, w.z, a.z); a.w = fmaf(zx, w.w, a.w);
                w = W1q[4 * kq + 1][sl];
                a.x = fmaf(zy, w.x, a.x); a.y = fmaf(zy, w.y, a.y);
                a.z = fmaf(zy, w.z, a.z); a.w = fmaf(zy, w.w, a.w);
                w = W1q[4 * kq + 2][sl];
                a.x = fmaf(zz, w.x, a.x); a.y = fmaf(zz, w.y, a.y);
                a.z = fmaf(zz, w.z, a.z); a.w = fmaf(zz, w.w, a.w);
                w = W1q[4 * kq + 3][sl];
                a.x = fmaf(zw, w.x, a.x); a.y = fmaf(zw, w.y, a.y);
                a.z = fmaf(zw, w.z, a.z); a.w = fmaf(zw, w.w, a.w);
            }
            z.x = fmaxf(a.x, 0.f);
            z.y = fmaxf(a.y, 0.f);
            z.z = fmaxf(a.z, 0.f);
            z.w = fmaxf(a.w, 0.f);
        }

        // matvec2: out = z @ W2 + b2
        float4 o = b2q[sl];
        #pragma unroll
        for (int kq = 0; kq < 8; kq++) {
            float zx = __shfl_sync(0xffffffffu, z.x, gb + kq);
            float zy = __shfl_sync(0xffffffffu, z.y, gb + kq);
            float zz = __shfl_sync(0xffffffffu, z.z, gb + kq);
            float zw = __shfl_sync(0xffffffffu, z.w, gb + kq);
            float4 w;
            w = W2q[4 * kq + 0][sl];
            o.x = fmaf(zx, w.x, o.x); o.y = fmaf(zx, w.y, o.y);
            o.z = fmaf(zx, w.z, o.z); o.w = fmaf(zx, w.w, o.w);
            w = W2q[4 * kq + 1][sl];
            o.x = fmaf(zy, w.x, o.x); o.y = fmaf(zy, w.y, o.y);
            o.z = fmaf(zy, w.z, o.z); o.w = fmaf(zy, w.w, o.w);
            w = W2q[4 * kq + 2][sl];
            o.x = fmaf(zz, w.x, o.x); o.y = fmaf(zz, w.y, o.y);
            o.z = fmaf(zz, w.z, o.z); o.w = fmaf(zz, w.w, o.w);
            w = W2q[4 * kq + 3][sl];
            o.x = fmaf(zw, w.x, o.x); o.y = fmaf(zw, w.y, o.y);
            o.z = fmaf(zw, w.z, o.z); o.w = fmaf(zw, w.w, o.w);
        }
        if (NMAT == 1) {
            o.x = (o.x > 0.f) ? o.x : expm1f(o.x);
            o.y = (o.y > 0.f) ? o.y : expm1f(o.y);
            o.z = (o.z > 0.f) ? o.z : expm1f(o.z);
            o.w = (o.w > 0.f) ? o.w : expm1f(o.w);
        } else {
            o.x = fmaxf(o.x, 0.f);
            o.y = fmaxf(o.y, 0.f);
            o.z = fmaxf(o.z, 0.f);
            o.w = fmaxf(o.w, 0.f);
        }
        *(float4*)(hout + (size_t)n * DIM + sl * 4) = o;
        lsum.x += o.x; lsq.x = fmaf(o.x, o.x, lsq.x);
        lsum.y += o.y; lsq.y = fmaf(o.y, o.y, lsq.y);
        lsum.z += o.z; lsq.z = fmaf(o.z, o.z, lsq.z);
        lsum.w += o.w; lsq.w = fmaf(o.w, o.w, lsq.w);
    }

    atomicAdd(&red[4 * sl + 0], lsum.x);
    atomicAdd(&red[4 * sl + 1], lsum.y);
    atomicAdd(&red[4 * sl + 2], lsum.z);
    atomicAdd(&red[4 * sl + 3], lsum.w);
    atomicAdd(&red[DIM + 4 * sl + 0], lsq.x);
    atomicAdd(&red[DIM + 4 * sl + 1], lsq.y);
    atomicAdd(&red[DIM + 4 * sl + 2], lsq.z);
    atomicAdd(&red[DIM + 4 * sl + 3], lsq.w);
    __syncthreads();
    if (tid < 2 * DIM)
        atomicAdd(&stat[tid], (double)red[tid]);
}

// Fused graph tail: inline layer-3 BN stats + pool + g2 + head; also re-zeroes deg.
__global__ void k_tail(const float* __restrict__ h,
                       const double* __restrict__ statp,
                       const int* __restrict__ goff,
                       const float* __restrict__ Wn2, const float* __restrict__ bn2b,
                       const float* __restrict__ t2,
                       const float* __restrict__ W4, const float* __restrict__ b4,
                       const float* __restrict__ W5, const float* __restrict__ b5,
                       float* __restrict__ outg,
                       float* __restrict__ out,
                       int* __restrict__ deg) {
    __shared__ float ss_s[2 * DIM];
    __shared__ float pacc[4][DIM];
    __shared__ float gs[DIM];
    __shared__ float xc[256];
    __shared__ float red[4];
    int b = blockIdx.x;
    int j = threadIdx.x;
    int wid = j >> 5, lane = j & 31;
    int zi = b * 128 + j;
    if (zi < N_NODES) deg[zi] = 0;
    if (j < 32) {
        double m = statp[j] * (1.0 / N_NODES);
        double v = statp[DIM + j] * (1.0 / N_NODES) - m * m;
        float sc = (float)(1.0 / sqrt(v + (double)BN_EPS));
        ss_s[j]       = sc;
        ss_s[DIM + j] = (float)(-m) * sc;
    }
    __syncthreads();
    int s0 = goff[b], s1 = goff[b + 1];
    float acc = 0.f;
    for (int n = s0 + wid; n < s1; n += 4) acc += h[n * DIM + lane];
    pacc[wid][lane] = acc;
    __syncthreads();
    if (wid == 0) {
        float a = pacc[0][lane] + pacc[1][lane] + pacc[2][lane] + pacc[3][lane];
        gs[lane] = fmaf(ss_s[lane], a, ss_s[DIM + lane] * (float)(s1 - s0));
    }
    __syncthreads();
    float a2 = bn2b[j];
    #pragma unroll
    for (int k = 0; k < DIM; k++) a2 = fmaf(gs[k], Wn2[k * H2 + j], a2);
    float g2v = fmaxf(a2, 0.f);
    outg[b * H2 + j] = g2v;
    xc[j]       = g2v;
    xc[128 + j] = t2[b * H2 + j];
    __syncthreads();
    float a4 = b4[j];
    #pragma unroll 4
    for (int k = 0; k < 256; k++) a4 = fmaf(xc[k], W4[k * H2 + j], a4);
    float y = fmaxf(a4, 0.f);
    float v = y * W5[j];
    for (int o = 16; o > 0; o >>= 1) v += __shfl_xor_sync(0xffffffffu, v, o);
    if (lane == 0) red[wid] = v;
    __syncthreads();
    if (j == 0) {
        float s = red[0] + red[1] + red[2] + red[3] + b5[0];
        out[b] = 1.f / (1.f + expf(-s));
    }
}

// ---------------- launch ----------------------------------------------------

extern "C" void kernel_launch(void* const* d_in, const int* in_sizes, int n_in,
                              void* d_out, int out_size) {
    const float* x       = (const float*)d_in[0];
    const int*   ei      = (const int*)d_in[1];
    const int*   batch   = (const int*)d_in[2];
    const float* target  = (const float*)d_in[3];
    const float* W11a = (const float*)d_in[4];   const float* b11a = (const float*)d_in[5];
    const float* W11b = (const float*)d_in[6];   const float* b11b = (const float*)d_in[7];
    const float* W12a = (const float*)d_in[8];   const float* b12a = (const float*)d_in[9];
    const float* W12b = (const float*)d_in[10];  const float* b12b = (const float*)d_in[11];
    const float* W13a = (const float*)d_in[12];  const float* b13a = (const float*)d_in[13];
    const float* W13b = (const float*)d_in[14];  const float* b13b = (const float*)d_in[15];
    const float* Wn2  = (const float*)d_in[16];  const float* bn2b = (const float*)d_in[17];
    const float* g1   = (const float*)d_in[18];  const float* be1  = (const float*)d_in[19];
    const float* W31  = (const float*)d_in[20];  const float* b31  = (const float*)d_in[21];
    const float* W32  = (const float*)d_in[22];  const float* b32  = (const float*)d_in[23];
    const float* W4   = (const float*)d_in[24];  const float* b4   = (const float*)d_in[25];
    const float* W5   = (const float*)d_in[26];  const float* b5   = (const float*)d_in[27];
    (void)in_sizes; (void)n_in; (void)out_size;

    const int* src = ei;
    const int* dst = ei + N_EDGES;

    float* out  = (float*)d_out;          // [0, 2048): sigmoid out
    float* outg = out + N_GRAPHS;         // [2048, ...): g2 [2048,128]

    void *pProj, *pHA, *pHB, *pStat, *pT1, *pT2, *pAB, *pDeg, *pAdj, *pGoff;
    cudaGetSymbolAddress(&pProj, d_proj);
    cudaGetSymbolAddress(&pHA,   d_hA);
    cudaGetSymbolAddress(&pHB,   d_hB);
    cudaGetSymbolAddress(&pStat, d_stat);
    cudaGetSymbolAddress(&pT1,   d_t1);
    cudaGetSymbolAddress(&pT2,   d_t2);
    cudaGetSymbolAddress(&pAB,   d_AB);
    cudaGetSymbolAddress(&pDeg,  d_deg);
    cudaGetSymbolAddress(&pAdj,  d_adj);
    cudaGetSymbolAddress(&pGoff, d_goff);

    float*  proj = (float*)pProj;
    float*  hA   = (float*)pHA;
    float*  hB   = (float*)pHB;
    double* stat = (double*)pStat;
    float*  t1b  = (float*)pT1;
    float*  t2b  = (float*)pT2;
    float*  ABb  = (float*)pAB;
    int*    deg  = (int*)pDeg;
    int*    adj  = (int*)pAdj;
    int*    goff = (int*)pGoff;

    const int BUILD_BLOCKS = EDGE_BLOCKS + GOFF_BLOCKS + 1 + T_DIM;

    // 1: build adjacency + goff + target BN stats + zero stats
    k_build<<<BUILD_BLOCKS, 256>>>(src, dst, deg, adj, batch, goff, target, g1, be1, ABb, stat);

    // 2: layer-1 input projection (78 -> 32)
    k_proj_in<<<PROJ_BLOCKS, 256>>>(x, W11a, proj);

    // 3: layer 1 (gather proj, W11b, elu) + piggyback t1 (front of grid)
    k_agg<1, 1><<<MLP_BLOCKS + T_BLOCKS, 256>>>(proj, deg, adj, (const double*)0,
                                                (const float*)0, b11a, W11b, b11b,
                                                hA, stat, target, ABb, W31, b31, t1b);

    // 4: layer 2 (gather hA, BN fold, W12a+W12b) + piggyback t2 (front of grid)
    k_agg<2, 2><<<MLP_BLOCKS + T_BLOCKS, 256>>>(hA, deg, adj, stat,
                                                W12a, b12a, W12b, b12b,
                                                hB, stat + 2 * DIM, t1b, ABb, W32, b32, t2b);

    // 5: layer 3 (gather hB, BN fold, W13a+W13b)
    k_agg<2, 0><<<MLP_BLOCKS, 256>>>(hB, deg, adj, stat + 2 * DIM,
                                     W13a, b13a, W13b, b13b,
                                     hA, stat + 4 * DIM, (const float*)0, (const float*)0,
                                     (const float*)0, (const float*)0, (float*)0);

    // 6: fused graph tail (inline layer-3 stats; re-zero deg for next replay)
    k_tail<<<N_GRAPHS, 128>>>(hA, stat + 4 * DIM, goff, Wn2, bn2b, t2b, W4, b4, W5, b5,
                              outg, out, deg);
}

// round 15
// speedup vs baseline: 1.5349x; 1.0668x over previous
#include <cuda_runtime.h>
#include <math.h>

#define N_NODES  100000
#define N_EDGES  1000000
#define N_GRAPHS 2048
#define F_IN     78
#define DIM      32
#define T_DIM    208
#define H1       170
#define H2       128
#define BN_EPS   1e-5f
#define DEG_CAP  64

// ---------------- scratch (device globals; no allocation allowed) ----------
__device__ float  d_proj[N_NODES * DIM];
__device__ float  d_hA[N_NODES * DIM];
__device__ float  d_hB[N_NODES * DIM];
__device__ double d_stat[3 * 2 * DIM];   // per layer: [sums(32), sumsq(32)]
__device__ float  d_t1[N_GRAPHS * H1];
__device__ float  d_t2[N_GRAPHS * H2];
__device__ float  d_AB[2 * T_DIM];
__device__ int    d_deg[N_NODES];        // zero at load; re-zeroed by k_tail
__device__ int    d_adj[N_NODES * DEG_CAP];
__device__ int    d_goff[N_GRAPHS + 1];

#define PROJ_BLOCKS  1024                                // merged into k_build
#define EDGE_BLOCKS  ((N_EDGES + 255) / 256)             // 3907
#define GOFF_BLOCKS  ((N_GRAPHS + 1 + 255) / 256)        // 9
#define T_BLOCKS     (N_GRAPHS / 16)                     // 128
#define MLP_BLOCKS   760                                 // +128 = 888 = 6*148 (one wave)
#define TAIL_BLOCKS  (N_GRAPHS / 16)                     // 128

// ---------------- build: input projection + adjacency + goff + target BN stats
__global__ void k_build(const int* __restrict__ src, const int* __restrict__ dst,
                        int* __restrict__ deg, int* __restrict__ adj,
                        const int* __restrict__ batch, int* __restrict__ goff,
                        const float* __restrict__ target,
                        const float* __restrict__ g1, const float* __restrict__ be1,
                        float* __restrict__ AB,
                        double* __restrict__ stat,
                        const float* __restrict__ x,
                        const float* __restrict__ Wp,
                        float* __restrict__ proj) {
    int b = blockIdx.x;
    if (b < PROJ_BLOCKS) {
        // proj = x @ Wp  (x: [N,78], Wp: [78,32]) ; one warp per node
        __shared__ float Ws[F_IN * DIM];
        for (int i = threadIdx.x; i < F_IN * DIM; i += blockDim.x) Ws[i] = Wp[i];
        __syncthreads();
        int lane = threadIdx.x & 31;
        int gwarp = (b * 256 + threadIdx.x) >> 5;
        const int nwarps = (PROJ_BLOCKS * 256) >> 5;
        for (int n = gwarp; n < N_NODES; n += nwarps) {
            const float* xr = x + (size_t)n * F_IN;
            float r0 = xr[lane];
            float r1 = xr[32 + lane];
            float r2 = (lane < F_IN - 64) ? xr[64 + lane] : 0.f;
            float acc = 0.f;
            #pragma unroll
            for (int k = 0; k < 32; k++)
                acc = fmaf(__shfl_sync(0xffffffffu, r0, k), Ws[k * DIM + lane], acc);
            #pragma unroll
            for (int k = 0; k < 32; k++)
                acc = fmaf(__shfl_sync(0xffffffffu, r1, k), Ws[(32 + k) * DIM + lane], acc);
            #pragma unroll
            for (int k = 0; k < F_IN - 64; k++)
                acc = fmaf(__shfl_sync(0xffffffffu, r2, k), Ws[(64 + k) * DIM + lane], acc);
            proj[n * DIM + lane] = acc;
        }
        return;
    }
    b -= PROJ_BLOCKS;
    if (b < EDGE_BLOCKS) {
        int i = b * 256 + threadIdx.x;
        if (i < N_EDGES) {
            int d = dst[i];
            int c = atomicAdd(&deg[d], 1);
            if (c < DEG_CAP) adj[d * DEG_CAP + c] = src[i];
        }
        return;
    }
    if (b < EDGE_BLOCKS + GOFF_BLOCKS) {
        int g = (b - EDGE_BLOCKS) * 256 + threadIdx.x;
        if (g > N_GRAPHS) return;
        int lo = 0, hi = N_NODES;
        while (lo < hi) { int mid = (lo + hi) >> 1; if (batch[mid] < g) lo = mid + 1; else hi = mid; }
        goff[g] = lo;
        return;
    }
    if (b < EDGE_BLOCKS + GOFF_BLOCKS + 1) {
        if (threadIdx.x < 3 * 2 * DIM) stat[threadIdx.x] = 0.0;
        return;
    }
    // target BN stats: one block per column
    int c = b - EDGE_BLOCKS - GOFF_BLOCKS - 1;
    float s = 0.f, q = 0.f;
    for (int r = threadIdx.x; r < N_GRAPHS; r += blockDim.x) {
        float v = target[r * T_DIM + c];
        s += v;
        q = fmaf(v, v, q);
    }
    __shared__ float ssm[256], sqm[256];
    ssm[threadIdx.x] = s; sqm[threadIdx.x] = q;
    __syncthreads();
    for (int st = 128; st > 0; st >>= 1) {
        if (threadIdx.x < st) { ssm[threadIdx.x] += ssm[threadIdx.x + st]; sqm[threadIdx.x] += sqm[threadIdx.x + st]; }
        __syncthreads();
    }
    if (threadIdx.x == 0) {
        float m = ssm[0] / (float)N_GRAPHS;
        float v = sqm[0] / (float)N_GRAPHS - m * m;
        float inv = rsqrtf(v + BN_EPS);
        float A = g1[c] * inv;
        AB[c]         = A;
        AB[T_DIM + c] = be1[c] - m * A;
    }
}

// Target-branch blocks, W-streaming form (TP: 1=t1 GEMM, 2=t2 GEMM+softmax).
template <int TP>
__device__ __forceinline__ void target_branch(int tb,
                          const float* __restrict__ tin,
                          const float* __restrict__ AB,
                          const float* __restrict__ Wt,
                          const float* __restrict__ bt,
                          float* __restrict__ tout) {
    if (TP == 1) {
        __shared__ float tn[16][T_DIM];
        const int row0 = tb * 16;
        for (int i = threadIdx.x; i < 16 * T_DIM; i += 256) {
            int r = i / T_DIM, c = i % T_DIM;
            tn[r][c] = fmaf(tin[(row0 + r) * T_DIM + c], AB[c], AB[T_DIM + c]);
        }
        __syncthreads();
        int j = threadIdx.x;
        if (j < H1) {
            float bj = bt[j];
            #pragma unroll
            for (int half = 0; half < 2; half++) {
                float acc[8];
                #pragma unroll
                for (int r = 0; r < 8; r++) acc[r] = bj;
                for (int c = 0; c < T_DIM; c++) {
                    float w = Wt[c * H1 + j];
                    #pragma unroll
                    for (int r = 0; r < 8; r++)
                        acc[r] = fmaf(tn[half * 8 + r][c], w, acc[r]);
                }
                #pragma unroll
                for (int r = 0; r < 8; r++)
                    tout[(row0 + half * 8 + r) * H1 + j] = acc[r];
            }
        }
    } else {
        __shared__ float t1s[16][H1 + 2];
        __shared__ float so[16][H2];
        const int row0 = tb * 16;
        for (int i = threadIdx.x; i < 16 * H1; i += 256) {
            int r = i / H1, c = i % H1;
            t1s[r][c] = tin[(row0 + r) * H1 + c];
        }
        __syncthreads();
        int j = threadIdx.x;
        if (j < H2) {
            float bj = bt[j];
            #pragma unroll
            for (int half = 0; half < 2; half++) {
                float acc[8];
                #pragma unroll
                for (int r = 0; r < 8; r++) acc[r] = bj;
                for (int c = 0; c < H1; c++) {
                    float w = Wt[c * H2 + j];
                    #pragma unroll
                    for (int r = 0; r < 8; r++)
                        acc[r] = fmaf(t1s[half * 8 + r][c], w, acc[r]);
                }
                #pragma unroll
                for (int r = 0; r < 8; r++)
                    so[half * 8 + r][j] = acc[r];
            }
        }
        __syncthreads();
        // softmax: each of 8 warps handles 2 rows; 4 values per lane
        int wid = threadIdx.x >> 5, lane = threadIdx.x & 31;
        #pragma unroll
        for (int rr = 0; rr < 2; rr++) {
            int r = wid * 2 + rr;
            float v0 = so[r][lane],      v1 = so[r][32 + lane];
            float v2 = so[r][64 + lane], v3 = so[r][96 + lane];
            float m = fmaxf(fmaxf(v0, v1), fmaxf(v2, v3));
            #pragma unroll
            for (int o = 16; o > 0; o >>= 1)
                m = fmaxf(m, __shfl_xor_sync(0xffffffffu, m, o));
            float e0 = expf(v0 - m), e1 = expf(v1 - m);
            float e2 = expf(v2 - m), e3 = expf(v3 - m);
            float s = (e0 + e1) + (e2 + e3);
            #pragma unroll
            for (int o = 16; o > 0; o >>= 1)
                s += __shfl_xor_sync(0xffffffffu, s, o);
            float inv = 1.f / s;
            tout[(row0 + r) * H2 + lane]      = e0 * inv;
            tout[(row0 + r) * H2 + 32 + lane] = e1 * inv;
            tout[(row0 + r) * H2 + 64 + lane] = e2 * inv;
            tout[(row0 + r) * H2 + 96 + lane] = e3 * inv;
        }
    }
}

// Fused GIN layer, 4 nodes per warp / float4 per lane (8 lanes per node).
// Gather: per-group loop to OWN degree; indices from int4 broadcast loads.
template <int NMAT, int TP>
__global__ void __launch_bounds__(256, 6)
k_agg(const float* __restrict__ hin,
      const int* __restrict__ deg,
      const int* __restrict__ adj,
      const double* __restrict__ statp,
      const float* __restrict__ W1,
      const float* __restrict__ b1,
      const float* __restrict__ W2,
      const float* __restrict__ b2,
      float* __restrict__ hout,
      double* __restrict__ stat,
      const float* __restrict__ tin,
      const float* __restrict__ AB,
      const float* __restrict__ Wt,
      const float* __restrict__ bt,
      float* __restrict__ tout) {
    if (TP != 0 && blockIdx.x < T_BLOCKS) {
        target_branch<TP>(blockIdx.x, tin, AB, Wt, bt, tout);
        return;
    }
    const int abid = (TP != 0) ? (blockIdx.x - T_BLOCKS) : blockIdx.x;

    __shared__ float4 W1q[DIM][8];
    __shared__ float4 W2q[DIM][8];
    __shared__ float4 baddq[8], b1q[8], b2q[8];
    __shared__ float  red[2 * DIM];

    float* W1f   = (float*)W1q;
    float* W2f   = (float*)W2q;
    float* badds = (float*)baddq;
    float* b1s   = (float*)b1q;
    float* b2s   = (float*)b2q;
    const int tid = threadIdx.x;

    if (tid < 32) {
        int j = tid;
        if (NMAT == 2) {
            double m = statp[j] * (1.0 / N_NODES);
            double v = statp[DIM + j] * (1.0 / N_NODES) - m * m;
            float sc = (float)(1.0 / sqrt(v + (double)BN_EPS));
            float sh = (float)(-m) * sc;
            float bacc = 0.f;
            #pragma unroll
            for (int k = 0; k < DIM; k++) {
                float w = W1[k * DIM + j];
                W1f[k * DIM + j] = __shfl_sync(0xffffffffu, sc, k) * w;
                bacc = fmaf(__shfl_sync(0xffffffffu, sh, k), w, bacc);
            }
            badds[j] = bacc;
        }
        b1s[j] = b1[j];
        b2s[j] = b2[j];
    }
    for (int i = tid; i < DIM * DIM; i += 256) W2f[i] = W2[i];
    if (tid < 2 * DIM) red[tid] = 0.f;
    __syncthreads();

    const int lane = tid & 31;
    const int g    = lane >> 3;    // node group 0..3
    const int sl   = lane & 7;     // feature quad 0..7
    const int gb   = g << 3;
    const int gwarp = (abid * 256 + tid) >> 5;
    const int stride4 = (MLP_BLOCKS * 8) * 4;
    float4 lsum = make_float4(0.f, 0.f, 0.f, 0.f);
    float4 lsq  = make_float4(0.f, 0.f, 0.f, 0.f);

    for (int n4 = gwarp * 4; n4 < N_NODES; n4 += stride4) {
        const int n = n4 + g;
        const int dT = deg[n];
        int dn = dT > DEG_CAP ? DEG_CAP : dT;
        const int* an = adj + (size_t)n * DEG_CAP;

        float4 z = *(const float4*)(hin + (size_t)n * DIM + sl * 4);

        for (int base = 0; base < dn; base += 8) {
            int4 i0 = *(const int4*)(an + base);
            int4 i1 = *(const int4*)(an + base + 4);
            int rem = dn - base;
            if (rem >= 8) {
                float4 t0 = *(const float4*)(hin + (size_t)i0.x * DIM + sl * 4);
                float4 t1 = *(const float4*)(hin + (size_t)i0.y * DIM + sl * 4);
                float4 t2 = *(const float4*)(hin + (size_t)i0.z * DIM + sl * 4);
                float4 t3 = *(const float4*)(hin + (size_t)i0.w * DIM + sl * 4);
                float4 t4 = *(const float4*)(hin + (size_t)i1.x * DIM + sl * 4);
                float4 t5 = *(const float4*)(hin + (size_t)i1.y * DIM + sl * 4);
                float4 t6 = *(const float4*)(hin + (size_t)i1.z * DIM + sl * 4);
                float4 t7 = *(const float4*)(hin + (size_t)i1.w * DIM + sl * 4);
                z.x += ((t0.x + t1.x) + (t2.x + t3.x)) + ((t4.x + t5.x) + (t6.x + t7.x));
                z.y += ((t0.y + t1.y) + (t2.y + t3.y)) + ((t4.y + t5.y) + (t6.y + t7.y));
                z.z += ((t0.z + t1.z) + (t2.z + t3.z)) + ((t4.z + t5.z) + (t6.z + t7.z));
                z.w += ((t0.w + t1.w) + (t2.w + t3.w)) + ((t4.w + t5.w) + (t6.w + t7.w));
            } else {
                #pragma unroll
                for (int k = 0; k < 7; k++) {
                    if (k < rem) {
                        int s = (k < 4) ? ((const int*)&i0)[k] : ((const int*)&i1)[k - 4];
                        float4 t = *(const float4*)(hin + (size_t)s * DIM + sl * 4);
                        z.x += t.x; z.y += t.y; z.z += t.z; z.w += t.w;
                    }
                }
            }
        }

        if (NMAT == 1) {
            float4 bb1 = b1q[sl];
            z.x = fmaxf(z.x + bb1.x, 0.f);
            z.y = fmaxf(z.y + bb1.y, 0.f);
            z.z = fmaxf(z.z + bb1.z, 0.f);
            z.w = fmaxf(z.w + bb1.w, 0.f);
        } else {
            float df = (float)(1 + dT);
            float4 bd  = baddq[sl];
            float4 bb1 = b1q[sl];
            float4 a;
            a.x = fmaf(df, bd.x, bb1.x);
            a.y = fmaf(df, bd.y, bb1.y);
            a.z = fmaf(df, bd.z, bb1.z);
            a.w = fmaf(df, bd.w, bb1.w);
            #pragma unroll
            for (int kq = 0; kq < 8; kq++) {
                float zx = __shfl_sync(0xffffffffu, z.x, gb + kq);
                float zy = __shfl_sync(0xffffffffu, z.y, gb + kq);
                float zz = __shfl_sync(0xffffffffu, z.z, gb + kq);
                float zw = __shfl_sync(0xffffffffu, z.w, gb + kq);
                float4 w;
                w = W1q[4 * kq + 0][sl];
                a.x = fmaf(zx, w.x, a.x); a.y = fmaf(zx, w.y, a.y);
                a.z = fmaf(zx, w.z, a.z); a.w = fmaf(zx, w.w, a.w);
                w = W1q[4 * kq + 1][sl];
                a.x = fmaf(zy, w.x, a.x); a.y = fmaf(zy, w.y, a.y);
                a.z = fmaf(zy, w.z, a.z); a.w = fmaf(zy, w.w, a.w);
                w = W1q[4 * kq + 2][sl];
                a.x = fmaf(zz, w.x, a.x); a.y = fmaf(zz, w.y, a.y);
                a.z = fmaf(zz, w.z, a.z); a.w = fmaf(zz, w.w, a.w);
                w = W1q[4 * kq + 3][sl];
                a.x = fmaf(zw, w.x, a.x); a.y = fmaf(zw, w.y, a.y);
                a.z = fmaf(zw, w.z, a.z); a.w = fmaf(zw, w.w, a.w);
            }
            z.x = fmaxf(a.x, 0.f);
            z.y = fmaxf(a.y, 0.f);
            z.z = fmaxf(a.z, 0.f);
            z.w = fmaxf(a.w, 0.f);
        }

        // matvec2: out = z @ W2 + b2
        float4 o = b2q[sl];
        #pragma unroll
        for (int kq = 0; kq < 8; kq++) {
            float zx = __shfl_sync(0xffffffffu, z.x, gb + kq);
            float zy = __shfl_sync(0xffffffffu, z.y, gb + kq);
            float zz = __shfl_sync(0xffffffffu, z.z, gb + kq);
            float zw = __shfl_sync(0xffffffffu, z.w, gb + kq);
            float4 w;
            w = W2q[4 * kq + 0][sl];
            o.x = fmaf(zx, w.x, o.x); o.y = fmaf(zx, w.y, o.y);
            o.z = fmaf(zx, w.z, o.z); o.w = fmaf(zx, w.w, o.w);
            w = W2q[4 * kq + 1][sl];
            o.x = fmaf(zy, w.x, o.x); o.y = fmaf(zy, w.y, o.y);
            o.z = fmaf(zy, w.z, o.z); o.w = fmaf(zy, w.w, o.w);
            w = W2q[4 * kq + 2][sl];
            o.x = fmaf(zz, w.x, o.x); o.y = fmaf(zz, w.y, o.y);
            o.z = fmaf(zz, w.z, o.z); o.w = fmaf(zz, w.w, o.w);
            w = W2q[4 * kq + 3][sl];
            o.x = fmaf(zw, w.x, o.x); o.y = fmaf(zw, w.y, o.y);
            o.z = fmaf(zw, w.z, o.z); o.w = fmaf(zw, w.w, o.w);
        }
        if (NMAT == 1) {
            o.x = (o.x > 0.f) ? o.x : expm1f(o.x);
            o.y = (o.y > 0.f) ? o.y : expm1f(o.y);
            o.z = (o.z > 0.f) ? o.z : expm1f(o.z);
            o.w = (o.w > 0.f) ? o.w : expm1f(o.w);
        } else {
            o.x = fmaxf(o.x, 0.f);
            o.y = fmaxf(o.y, 0.f);
            o.z = fmaxf(o.z, 0.f);
            o.w = fmaxf(o.w, 0.f);
        }
        *(float4*)(hout + (size_t)n * DIM + sl * 4) = o;
        lsum.x += o.x; lsq.x = fmaf(o.x, o.x, lsq.x);
        lsum.y += o.y; lsq.y = fmaf(o.y, o.y, lsq.y);
        lsum.z += o.z; lsq.z = fmaf(o.z, o.z, lsq.z);
        lsum.w += o.w; lsq.w = fmaf(o.w, o.w, lsq.w);
    }

    atomicAdd(&red[4 * sl + 0], lsum.x);
    atomicAdd(&red[4 * sl + 1], lsum.y);
    atomicAdd(&red[4 * sl + 2], lsum.z);
    atomicAdd(&red[4 * sl + 3], lsum.w);
    atomicAdd(&red[DIM + 4 * sl + 0], lsq.x);
    atomicAdd(&red[DIM + 4 * sl + 1], lsq.y);
    atomicAdd(&red[DIM + 4 * sl + 2], lsq.z);
    atomicAdd(&red[DIM + 4 * sl + 3], lsq.w);
    __syncthreads();
    if (tid < 2 * DIM)
        atomicAdd(&stat[tid], (double)red[tid]);
}

// Fused graph tail, W-streaming form: 16 graphs per block (128 blocks).
// Pool + BN + g2 GEMM + head GEMM; Wn2/W4 each read ONCE per block.
__global__ void __launch_bounds__(256)
k_tail(const float* __restrict__ h,
       const double* __restrict__ statp,
       const int* __restrict__ goff,
       const float* __restrict__ Wn2, const float* __restrict__ bn2b,
       const float* __restrict__ t2,
       const float* __restrict__ W4, const float* __restrict__ b4,
       const float* __restrict__ W5, const float* __restrict__ b5,
       float* __restrict__ outg,
       float* __restrict__ out,
       int* __restrict__ deg) {
    __shared__ float ss_s[2 * DIM];
    __shared__ float gs[16][DIM];
    __shared__ float xc[16][256];
    __shared__ float part[16][128];
    __shared__ float yv[16][128];
    const int tid = threadIdx.x;
    const int b0 = blockIdx.x * 16;
    // re-zero deg for the next graph replay
    for (int i = blockIdx.x * 256 + tid; i < N_NODES; i += TAIL_BLOCKS * 256)
        deg[i] = 0;
    if (tid < 32) {
        double m = statp[tid] * (1.0 / N_NODES);
        double v = statp[DIM + tid] * (1.0 / N_NODES) - m * m;
        float sc = (float)(1.0 / sqrt(v + (double)BN_EPS));
        ss_s[tid]       = sc;
        ss_s[DIM + tid] = (float)(-m) * sc;
    }
    __syncthreads();
    const int wid = tid >> 5, lane = tid & 31;
    // pool: 8 warps x 2 graphs each
    #pragma unroll
    for (int gg = 0; gg < 2; gg++) {
        int gi = wid * 2 + gg;
        int gr = b0 + gi;
        int s0 = goff[gr], s1 = goff[gr + 1];
        float acc = 0.f;
        for (int n = s0; n < s1; n++) acc += h[n * DIM + lane];
        gs[gi][lane] = fmaf(ss_s[lane], acc, ss_s[DIM + lane] * (float)(s1 - s0));
    }
    __syncthreads();
    // g2 = relu(gs @ Wn2 + bn2b): threads 0-127 compute; 128-255 stage t2
    if (tid < 128) {
        float acc[16];
        float bj = bn2b[tid];
        #pragma unroll
        for (int r = 0; r < 16; r++) acc[r] = bj;
        for (int k = 0; k < DIM; k++) {
            float w = Wn2[k * H2 + tid];
            #pragma unroll
            for (int r = 0; r < 16; r++) acc[r] = fmaf(gs[r][k], w, acc[r]);
        }
        #pragma unroll
        for (int r = 0; r < 16; r++) {
            float v = fmaxf(acc[r], 0.f);
            outg[(b0 + r) * H2 + tid] = v;
            xc[r][tid] = v;
        }
    } else {
        int j = tid - 128;
        #pragma unroll
        for (int r = 0; r < 16; r++)
            xc[r][128 + j] = t2[(b0 + r) * H2 + j];
    }
    __syncthreads();
    // head GEMM, split-K over thread halves; W4 streamed once
    {
        int j = tid & 127;
        int half = tid >> 7;
        float acc[16];
        #pragma unroll
        for (int r = 0; r < 16; r++) acc[r] = 0.f;
        int k0 = half * 128;
        for (int k = k0; k < k0 + 128; k++) {
            float w = W4[k * H2 + j];
            #pragma unroll
            for (int r = 0; r < 16; r++) acc[r] = fmaf(xc[r][k], w, acc[r]);
        }
        if (half == 1) {
            #pragma unroll
            for (int r = 0; r < 16; r++) part[r][j] = acc[r];
        }
        __syncthreads();
        if (half == 0) {
            float bj = b4[j];
            float w5 = W5[j];
            #pragma unroll
            for (int r = 0; r < 16; r++) {
                float y = fmaxf(acc[r] + part[r][j] + bj, 0.f);
                yv[r][j] = y * w5;
            }
        }
    }
    __syncthreads();
    // reduce yv rows: 8 warps x 2 rows
    #pragma unroll
    for (int gg = 0; gg < 2; gg++) {
        int r = wid * 2 + gg;
        float v = (yv[r][lane] + yv[r][32 + lane]) + (yv[r][64 + lane] + yv[r][96 + lane]);
        #pragma unroll
        for (int o = 16; o > 0; o >>= 1) v += __shfl_xor_sync(0xffffffffu, v, o);
        if (lane == 0) out[b0 + r] = 1.f / (1.f + expf(-(v + b5[0])));
    }
}

// ---------------- launch ----------------------------------------------------

extern "C" void kernel_launch(void* const* d_in, const int* in_sizes, int n_in,
                              void* d_out, int out_size) {
    const float* x       = (const float*)d_in[0];
    const int*   ei      = (const int*)d_in[1];
    const int*   batch   = (const int*)d_in[2];
    const float* target  = (const float*)d_in[3];
    const float* W11a = (const float*)d_in[4];   const float* b11a = (const float*)d_in[5];
    const float* W11b = (const float*)d_in[6];   const float* b11b = (const float*)d_in[7];
    const float* W12a = (const float*)d_in[8];   const float* b12a = (const float*)d_in[9];
    const float* W12b = (const float*)d_in[10];  const float* b12b = (const float*)d_in[11];
    const float* W13a = (const float*)d_in[12];  const float* b13a = (const float*)d_in[13];
    const float* W13b = (const float*)d_in[14];  const float* b13b = (const float*)d_in[15];
    const float* Wn2  = (const float*)d_in[16];  const float* bn2b = (const float*)d_in[17];
    const float* g1   = (const float*)d_in[18];  const float* be1  = (const float*)d_in[19];
    const float* W31  = (const float*)d_in[20];  const float* b31  = (const float*)d_in[21];
    const float* W32  = (const float*)d_in[22];  const float* b32  = (const float*)d_in[23];
    const float* W4   = (const float*)d_in[24];  const float* b4   = (const float*)d_in[25];
    const float* W5   = (const float*)d_in[26];  const float* b5   = (const float*)d_in[27];
    (void)in_sizes; (void)n_in; (void)out_size;

    const int* src = ei;
    const int* dst = ei + N_EDGES;

    float* out  = (float*)d_out;          // [0, 2048): sigmoid out
    float* outg = out + N_GRAPHS;         // [2048, ...): g2 [2048,128]

    void *pProj, *pHA, *pHB, *pStat, *pT1, *pT2, *pAB, *pDeg, *pAdj, *pGoff;
    cudaGetSymbolAddress(&pProj, d_proj);
    cudaGetSymbolAddress(&pHA,   d_hA);
    cudaGetSymbolAddress(&pHB,   d_hB);
    cudaGetSymbolAddress(&pStat, d_stat);
    cudaGetSymbolAddress(&pT1,   d_t1);
    cudaGetSymbolAddress(&pT2,   d_t2);
    cudaGetSymbolAddress(&pAB,   d_AB);
    cudaGetSymbolAddress(&pDeg,  d_deg);
    cudaGetSymbolAddress(&pAdj,  d_adj);
    cudaGetSymbolAddress(&pGoff, d_goff);

    float*  proj = (float*)pProj;
    float*  hA   = (float*)pHA;
    float*  hB   = (float*)pHB;
    double* stat = (double*)pStat;
    float*  t1b  = (float*)pT1;
    float*  t2b  = (float*)pT2;
    float*  ABb  = (float*)pAB;
    int*    deg  = (int*)pDeg;
    int*    adj  = (int*)pAdj;
    int*    goff = (int*)pGoff;

    const int BUILD_BLOCKS = PROJ_BLOCKS + EDGE_BLOCKS + GOFF_BLOCKS + 1 + T_DIM;

    // 1: input projection + adjacency + goff + target BN stats + zero stats
    k_build<<<BUILD_BLOCKS, 256>>>(src, dst, deg, adj, batch, goff, target, g1, be1,
                                   ABb, stat, x, W11a, proj);

    // 2: layer 1 (gather proj, W11b, elu) + piggyback t1 (front of grid)
    k_agg<1, 1><<<MLP_BLOCKS + T_BLOCKS, 256>>>(proj, deg, adj, (const double*)0,
                                                (const float*)0, b11a, W11b, b11b,
                                                hA, stat, target, ABb, W31, b31, t1b);

    // 3: layer 2 (gather hA, BN fold, W12a+W12b) + piggyback t2 (front of grid)
    k_agg<2, 2><<<MLP_BLOCKS + T_BLOCKS, 256>>>(hA, deg, adj, stat,
                                                W12a, b12a, W12b, b12b,
                                                hB, stat + 2 * DIM, t1b, ABb, W32, b32, t2b);

    // 4: layer 3 (gather hB, BN fold, W13a+W13b)
    k_agg<2, 0><<<MLP_BLOCKS, 256>>>(hB, deg, adj, stat + 2 * DIM,
                                     W13a, b13a, W13b, b13b,
                                     hA, stat + 4 * DIM, (const float*)0, (const float*)0,
                                     (const float*)0, (const float*)0, (float*)0);

    // 5: fused graph tail (W-streaming; inline layer-3 stats; re-zero deg)
    k_tail<<<TAIL_BLOCKS, 256>>>(hA, stat + 4 * DIM, goff, Wn2, bn2b, t2b, W4, b4, W5, b5,
                                 outg, out, deg);
}